// round 3
// baseline (speedup 1.0000x reference)
#include <cuda_runtime.h>

#define NC 4096          // current rows
#define NH 8192          // historical rows
#define NT 12288         // NC + NH
#define FD 512           // feature dim
#define RD 128           // reduced dim
#define NL 3             // levels

#define BQ  32           // flash: queries per block
#define BKV 64           // flash: keys per tile
#define KVS 516          // padded K/V smem row stride (floats; 2064B = 129*16, keeps 16B align)
#define PSS 65           // padded score smem row stride (floats)
#define FLASH_SMEM ((BQ*FD + BKV*KVS + BQ*PSS + 3*BQ) * sizeof(float))

typedef unsigned long long u64;

// ---- packed f32x2 helpers (sm_103a FFMA2 path; ptxas never auto-fuses) ----
__device__ __forceinline__ u64 pk2(float v) {
    u64 r; asm("mov.b64 %0, {%1, %1};" : "=l"(r) : "f"(v)); return r;
}
__device__ __forceinline__ void fma2(u64& d, u64 a, u64 b) {
    asm("fma.rn.f32x2 %0, %1, %2, %0;" : "+l"(d) : "l"(a), "l"(b));
}
__device__ __forceinline__ void mul2(u64& d, u64 a, u64 b) {
    asm("mul.rn.f32x2 %0, %1, %2;" : "=l"(d) : "l"(a), "l"(b));
}
__device__ __forceinline__ float2 upk(u64 v) {
    float2 r; asm("mov.b64 {%0, %1}, %2;" : "=f"(r.x), "=f"(r.y) : "l"(v)); return r;
}

// -------- scratch (device globals; no allocation APIs anywhere) --------
__device__ float g_h[(size_t)NT * RD];            // per-level hidden, reused
__device__ float g_proj[(size_t)NL * NT * FD];    // all-level projections
__device__ float g_att[(size_t)NC * (NL * FD)];   // concat attention output

// ======================================================================
// Tiled SGEMM:  C[M,N] = act(A[M,K] @ B[N,K]^T + bias[N])
// BM=64, BN=128, BK=32, 256 threads, 4x8 register tile (packed f32x2).
// All M,N,K here are multiples of the tile sizes -> no bounds checks.
// ======================================================================
template<bool RELU>
__global__ __launch_bounds__(256)
void gemm_bt(const float* __restrict__ A, const float* __restrict__ B,
             const float* __restrict__ bias, float* __restrict__ C,
             int M, int N, int K)
{
    __shared__ __align__(16) float As[64 * 36];    // padded stride 36
    __shared__ __align__(16) float Bs[32 * 132];   // transposed, stride 132 (528B = 33*16)

    const int tid = threadIdx.x;
    const int m0 = blockIdx.y * 64;
    const int n0 = blockIdx.x * 128;
    const int ty = tid >> 4;         // 0..15
    const int tx = tid & 15;         // 0..15
    const int kq = tid & 7;          // 0..7   (k quad for loads)
    const int lr = tid >> 3;         // 0..31  (row for loads)

    u64 acc[4][4];                   // 4 rows x 8 cols as 4 packed pairs
#pragma unroll
    for (int i = 0; i < 4; ++i)
#pragma unroll
        for (int j = 0; j < 4; ++j) acc[i][j] = 0ull;

    for (int k0 = 0; k0 < K; k0 += 32) {
        // A tile: 64 rows x 32 k
#pragma unroll
        for (int it = 0; it < 2; ++it) {
            int m = lr + it * 32;
            float4 v = *(const float4*)(A + (size_t)(m0 + m) * K + k0 + kq * 4);
            *(float4*)(As + m * 36 + kq * 4) = v;
        }
        // B tile: 128 rows x 32 k, stored transposed Bs[k][n]
#pragma unroll
        for (int it = 0; it < 4; ++it) {
            int n = lr + it * 32;
            float4 v = *(const float4*)(B + (size_t)(n0 + n) * K + k0 + kq * 4);
            Bs[(kq * 4 + 0) * 132 + n] = v.x;
            Bs[(kq * 4 + 1) * 132 + n] = v.y;
            Bs[(kq * 4 + 2) * 132 + n] = v.z;
            Bs[(kq * 4 + 3) * 132 + n] = v.w;
        }
        __syncthreads();

#pragma unroll
        for (int k = 0; k < 32; ++k) {
            ulonglong2 b0 = *(const ulonglong2*)(Bs + k * 132 + tx * 8);
            ulonglong2 b1 = *(const ulonglong2*)(Bs + k * 132 + tx * 8 + 4);
#pragma unroll
            for (int i = 0; i < 4; ++i) {
                u64 ap = pk2(As[(ty * 4 + i) * 36 + k]);
                fma2(acc[i][0], ap, b0.x);
                fma2(acc[i][1], ap, b0.y);
                fma2(acc[i][2], ap, b1.x);
                fma2(acc[i][3], ap, b1.y);
            }
        }
        __syncthreads();
    }

#pragma unroll
    for (int i = 0; i < 4; ++i) {
        int row = m0 + ty * 4 + i;
        float v[8];
#pragma unroll
        for (int j = 0; j < 4; ++j) {
            float2 p = upk(acc[i][j]);
            v[j * 2]     = p.x + bias[n0 + tx * 8 + j * 2];
            v[j * 2 + 1] = p.y + bias[n0 + tx * 8 + j * 2 + 1];
            if (RELU) {
                v[j * 2]     = fmaxf(v[j * 2], 0.f);
                v[j * 2 + 1] = fmaxf(v[j * 2 + 1], 0.f);
            }
        }
        *(float4*)(C + (size_t)row * N + n0 + tx * 8)     = make_float4(v[0], v[1], v[2], v[3]);
        *(float4*)(C + (size_t)row * N + n0 + tx * 8 + 4) = make_float4(v[4], v[5], v[6], v[7]);
    }
}

// ======================================================================
// Fused flash attention per level.
// grid = (NC/BQ, NL), 256 threads.
// Q = proj[level][0..NC),  K = proj[level][NC..NT),  V = raw historical feats.
// Out written into g_att concat layout: row stride NL*FD, col offset level*FD.
// All heavy inner loops use packed f32x2 FMA.
// ======================================================================
__global__ __launch_bounds__(256)
void flash_kernel(const float* __restrict__ proj,
                  const float* __restrict__ hist,
                  float* __restrict__ att)
{
    extern __shared__ __align__(16) float sm[];
    float* Qs  = sm;                     // [BQ][FD]
    float* KVs = Qs + BQ * FD;           // [BKV][KVS]  (K, then V)
    float* Ps  = KVs + BKV * KVS;        // [BQ][PSS]
    float* m_s = Ps + BQ * PSS;          // [BQ]
    float* l_s = m_s + BQ;               // [BQ]
    float* a_s = l_s + BQ;               // [BQ]

    const int t = threadIdx.x;
    const int level = blockIdx.y;
    const int qb = blockIdx.x * BQ;

    const float* Q  = proj + (size_t)level * NT * FD;
    const float* Kp = Q + (size_t)NC * FD;
    float* Out = att + level * FD;

    const float scale = 0.044194173824159216f;   // 1/sqrt(512)

    // load Q tile (once)
#pragma unroll
    for (int it = 0; it < 16; ++it) {
        int idx = it * 256 + t;
        int r = idx >> 7;
        int c = (idx & 127) << 2;
        *(float4*)(Qs + r * FD + c) = *(const float4*)(Q + (size_t)(qb + r) * FD + c);
    }
    if (t < BQ) { m_s[t] = -1e30f; l_s[t] = 0.f; }

    const int q0 = (t >> 4) << 1;   // S-phase: q pair; O-phase: same pair
    const int kg = t & 15;          // S-phase: k lane
    const int dg = (t & 15) << 2;   // O-phase: d base (float4, stride 64)

    u64 o0[16], o1[16];             // O accumulators: 2 q rows x 32 d (packed)
#pragma unroll
    for (int c = 0; c < 16; ++c) { o0[c] = 0ull; o1[c] = 0ull; }

    __syncthreads();

    for (int kt = 0; kt < NH; kt += BKV) {
        // ---- load K tile ----
#pragma unroll 4
        for (int it = 0; it < 32; ++it) {
            int idx = it * 256 + t;
            int r = idx >> 7;
            int c = (idx & 127) << 2;
            *(float4*)(KVs + r * KVS + c) = *(const float4*)(Kp + (size_t)(kt + r) * FD + c);
        }
        __syncthreads();

        // ---- S = Q.K^T * scale  (each thread: 2 q x 4 k dots of 512, packed) ----
        u64 s0[4] = {0ull, 0ull, 0ull, 0ull};
        u64 s1[4] = {0ull, 0ull, 0ull, 0ull};
        const float* qp0 = Qs + q0 * FD;
        const float* qp1 = qp0 + FD;
#pragma unroll 8
        for (int d = 0; d < FD; d += 4) {
            ulonglong2 qa = *(const ulonglong2*)(qp0 + d);
            ulonglong2 qc = *(const ulonglong2*)(qp1 + d);
#pragma unroll
            for (int kk = 0; kk < 4; ++kk) {
                ulonglong2 kv = *(const ulonglong2*)(KVs + (kg + kk * 16) * KVS + d);
                fma2(s0[kk], qa.x, kv.x);
                fma2(s0[kk], qa.y, kv.y);
                fma2(s1[kk], qc.x, kv.x);
                fma2(s1[kk], qc.y, kv.y);
            }
        }
#pragma unroll
        for (int kk = 0; kk < 4; ++kk) {
            float2 a = upk(s0[kk]);
            float2 b = upk(s1[kk]);
            Ps[q0 * PSS + kg + kk * 16]       = (a.x + a.y) * scale;
            Ps[(q0 + 1) * PSS + kg + kk * 16] = (b.x + b.y) * scale;
        }
        __syncthreads();   // S done: safe to overwrite KVs with V

        // ---- load V tile (all threads) + online softmax (warp 0) ----
#pragma unroll 4
        for (int it = 0; it < 32; ++it) {
            int idx = it * 256 + t;
            int r = idx >> 7;
            int c = (idx & 127) << 2;
            *(float4*)(KVs + r * KVS + c) = *(const float4*)(hist + (size_t)(kt + r) * FD + c);
        }
        if (t < BQ) {
            float mo = m_s[t];
            float mx = mo;
            float* pr = Ps + t * PSS;
#pragma unroll 8
            for (int j = 0; j < BKV; ++j) mx = fmaxf(mx, pr[j]);
            float al = __expf(mo - mx);
            float sum = 0.f;
#pragma unroll 8
            for (int j = 0; j < BKV; ++j) {
                float p = __expf(pr[j] - mx);
                pr[j] = p;
                sum += p;
            }
            m_s[t] = mx;
            a_s[t] = al;
            l_s[t] = fmaf(l_s[t], al, sum);
        }
        __syncthreads();

        // ---- O = O*alpha + P.V  (thread: 2 q x 32 d, packed) ----
        u64 al0 = pk2(a_s[q0]);
        u64 al1 = pk2(a_s[q0 + 1]);
#pragma unroll
        for (int c = 0; c < 16; ++c) {
            mul2(o0[c], o0[c], al0);
            mul2(o1[c], o1[c], al1);
        }
        const float* p0r = Ps + q0 * PSS;
        const float* p1r = p0r + PSS;
#pragma unroll 4
        for (int j = 0; j < BKV; ++j) {
            u64 p0 = pk2(p0r[j]);
            u64 p1 = pk2(p1r[j]);
            const float* vp = KVs + j * KVS + dg;
#pragma unroll
            for (int c = 0; c < 8; ++c) {
                ulonglong2 vv = *(const ulonglong2*)(vp + (c << 6));
                fma2(o0[2 * c],     p0, vv.x);
                fma2(o0[2 * c + 1], p0, vv.y);
                fma2(o1[2 * c],     p1, vv.x);
                fma2(o1[2 * c + 1], p1, vv.y);
            }
        }
        __syncthreads();   // before next K tile overwrites KVs / Ps
    }

    // ---- normalize + write concat layout ----
    float inv0 = 1.f / l_s[q0];
    float inv1 = 1.f / l_s[q0 + 1];
#pragma unroll
    for (int c = 0; c < 8; ++c) {
        float2 a0 = upk(o0[2 * c]);
        float2 a1 = upk(o0[2 * c + 1]);
        float2 b0 = upk(o1[2 * c]);
        float2 b1 = upk(o1[2 * c + 1]);
        float4 v0 = make_float4(a0.x * inv0, a0.y * inv0, a1.x * inv0, a1.y * inv0);
        float4 v1 = make_float4(b0.x * inv1, b0.y * inv1, b1.x * inv1, b1.y * inv1);
        *(float4*)(Out + (size_t)(qb + q0)     * (NL * FD) + dg + (c << 6)) = v0;
        *(float4*)(Out + (size_t)(qb + q0 + 1) * (NL * FD) + dg + (c << 6)) = v1;
    }
}

// ======================================================================
extern "C" void kernel_launch(void* const* d_in, const int* in_sizes, int n_in,
                              void* d_out, int out_size)
{
    const float* cur  = (const float*)d_in[0];   // [4096, 512]
    const float* hist = (const float*)d_in[1];   // [8192, 512]
    const float* W1   = (const float*)d_in[2];   // [3, 128, 512]
    const float* b1   = (const float*)d_in[3];   // [3, 128]
    const float* W2   = (const float*)d_in[4];   // [3, 512, 128]
    const float* b2   = (const float*)d_in[5];   // [3, 512]
    const float* Wf   = (const float*)d_in[6];   // [512, 1536]
    const float* bf   = (const float*)d_in[7];   // [512]
    float* out = (float*)d_out;                  // [4096, 512]

    float *ph, *pp, *pa;
    cudaGetSymbolAddress((void**)&ph, g_h);
    cudaGetSymbolAddress((void**)&pp, g_proj);
    cudaGetSymbolAddress((void**)&pa, g_att);

    cudaFuncSetAttribute(flash_kernel,
                         cudaFuncAttributeMaxDynamicSharedMemorySize,
                         (int)FLASH_SMEM);

    for (int l = 0; l < NL; ++l) {
        const float* W1l = W1 + (size_t)l * RD * FD;
        const float* b1l = b1 + (size_t)l * RD;
        const float* W2l = W2 + (size_t)l * FD * RD;
        const float* b2l = b2 + (size_t)l * FD;
        float* projl = pp + (size_t)l * NT * FD;

        // H = relu(X @ W1^T + b1)   (current rows, then historical rows)
        gemm_bt<true><<<dim3(RD / 128, NC / 64), 256>>>(cur,  W1l, b1l, ph, NC, RD, FD);
        gemm_bt<true><<<dim3(RD / 128, NH / 64), 256>>>(hist, W1l, b1l,
                                                        ph + (size_t)NC * RD, NH, RD, FD);
        // proj = H @ W2^T + b2
        gemm_bt<false><<<dim3(FD / 128, NT / 64), 256>>>(ph, W2l, b2l, projl, NT, FD, RD);
    }

    // fused flash attention over all levels
    flash_kernel<<<dim3(NC / BQ, NL), 256, FLASH_SMEM>>>(pp, hist, pa);

    // out = concat @ Wf^T + bf
    gemm_bt<false><<<dim3(FD / 128, NC / 64), 256>>>(pa, Wf, bf, out, NC, FD, NL * FD);
}

// round 5
// speedup vs baseline: 5.8062x; 5.8062x over previous
#include <cuda_runtime.h>
#include <cuda_bf16.h>

#define NC 4096
#define NH 8192
#define NT 12288
#define FD 512
#define RD 128
#define NL 3

typedef unsigned long long u64;
typedef unsigned int u32;

#define KC 64                    // k elements per chunk
#define TILE_B 16384             // one operand tile: 128 rows x 64 bf16 = 16KB
#define STAGE_B (4 * TILE_B)     // Ahi, Alo, Bhi, Blo
#define GSMEM (2 * STAGE_B)      // double-buffered: 128KB

// ---------------- helpers ----------------
__device__ __forceinline__ u32 smem_u32(const void* p) {
    u32 a;
    asm("{ .reg .u64 t; cvta.to.shared.u64 t, %1; cvt.u32.u64 %0, t; }" : "=r"(a) : "l"(p));
    return a;
}
__device__ __forceinline__ void ldsm4(u32* r, u32 addr) {
    asm volatile("ldmatrix.sync.aligned.m8n8.x4.shared.b16 {%0,%1,%2,%3}, [%4];"
                 : "=r"(r[0]), "=r"(r[1]), "=r"(r[2]), "=r"(r[3]) : "r"(addr));
}
__device__ __forceinline__ void mma_bf16(float* c, const u32* a, const u32* b) {
    asm volatile("mma.sync.aligned.m16n8k16.row.col.f32.bf16.bf16.f32 "
                 "{%0,%1,%2,%3}, {%4,%5,%6,%7}, {%8,%9}, {%0,%1,%2,%3};"
                 : "+f"(c[0]), "+f"(c[1]), "+f"(c[2]), "+f"(c[3])
                 : "r"(a[0]), "r"(a[1]), "r"(a[2]), "r"(a[3]), "r"(b[0]), "r"(b[1]));
}
// swizzled smem byte address for (row, k) in a [128][64] bf16 tile (k multiple of 8)
__device__ __forceinline__ u32 swz(u32 base, u32 row, u32 k) {
    return base + row * 128 + ((((k >> 3) ^ (row & 7)) & 7) << 4);
}

// ---------------- scratch (no allocation APIs anywhere) ----------------
__device__ __align__(128) __nv_bfloat16 g_Xhi[(size_t)NT * FD],  g_Xlo[(size_t)NT * FD];
__device__ __align__(128) __nv_bfloat16 g_Hhi[(size_t)NT * RD],  g_Hlo[(size_t)NT * RD];
__device__ __align__(128) __nv_bfloat16 g_Phi[(size_t)NT * FD],  g_Plo[(size_t)NT * FD];
__device__ __align__(128) __nv_bfloat16 g_Thi[(size_t)FD * NH],  g_Tlo[(size_t)FD * NH];
__device__ __align__(128) float         g_S  [(size_t)NC * NH];
__device__ __align__(128) __nv_bfloat16 g_AThi[(size_t)NC * NH], g_ATlo[(size_t)NC * NH];
__device__ __align__(128) __nv_bfloat16 g_Ohi[(size_t)NC * NL * FD], g_Olo[(size_t)NC * NL * FD];
__device__ __align__(128) __nv_bfloat16 g_W1hi[(size_t)NL * RD * FD], g_W1lo[(size_t)NL * RD * FD];
__device__ __align__(128) __nv_bfloat16 g_W2hi[(size_t)NL * FD * RD], g_W2lo[(size_t)NL * FD * RD];
__device__ __align__(128) __nv_bfloat16 g_Wfhi[(size_t)FD * NL * FD], g_Wflo[(size_t)FD * NL * FD];

// ======================================================================
// Split-bf16 HMMA GEMM: C[M,N] = act(A[M,K] @ B[N,K]^T + bias)
// A ~= Ahi+Alo, B ~= Bhi+Blo (bf16 splits of fp32, row-major, ld = K).
// 3 mma products (hh, hl, lh) into fp32 accumulators.
// CTA tile 128x128, Kc=64, cp.async 2-stage pipeline, 256 threads,
// 8 warps in 2(m) x 4(n) grid, warp tile 64x32.
// ======================================================================
template<bool RELU, bool WF32, bool WSPLIT>
__global__ __launch_bounds__(256, 1)
void mm128(const __nv_bfloat16* __restrict__ Ahi, const __nv_bfloat16* __restrict__ Alo,
           const __nv_bfloat16* __restrict__ Bhi, const __nv_bfloat16* __restrict__ Blo,
           const float* __restrict__ bias,
           float* __restrict__ C, int ldc,
           __nv_bfloat16* __restrict__ Chi, __nv_bfloat16* __restrict__ Clo, int ldcs,
           int K)
{
    extern __shared__ __align__(1024) char smem[];
    const int tid  = threadIdx.x;
    const int wid  = tid >> 5;
    const int lane = tid & 31;
    const int m0 = blockIdx.y * 128;
    const int n0 = blockIdx.x * 128;
    const int wm = (wid & 1) * 64;     // warp m offset in CTA tile
    const int wn = (wid >> 1) * 32;    // warp n offset in CTA tile

    const u32 sbase = smem_u32(smem);

    const __nv_bfloat16* srcs[4] = { Ahi + (size_t)m0 * K, Alo + (size_t)m0 * K,
                                     Bhi + (size_t)n0 * K, Blo + (size_t)n0 * K };

    float acc[4][4][4];
#pragma unroll
    for (int i = 0; i < 4; ++i)
#pragma unroll
        for (int j = 0; j < 4; ++j)
#pragma unroll
            for (int h = 0; h < 4; ++h) acc[i][j][h] = 0.f;

    // ldmatrix lane addressing
    const u32 a_row = lane & 15;             // A: x4 = (rows 0-7,kb0)(8-15,kb0)(0-7,kb8)(8-15,kb8)
    const u32 a_k   = (lane >> 4) << 3;
    const u32 b_row = ((lane >> 4) << 3) + (lane & 7);  // B: x4 = nt0/kb0, nt0/kb8, nt1/kb0, nt1/kb8
    const u32 b_k   = ((lane >> 3) & 1) << 3;

    const int nch = K / KC;

    auto load_chunk = [&](int c, int buf) {
        const int kb = c * KC;
        const u32 sb = sbase + buf * STAGE_B;
#pragma unroll
        for (int i = 0; i < 16; ++i) {
            const int t  = i >> 2;
            const int cc = ((i & 3) << 8) + tid;       // 0..1023 (16B chunks per tile)
            const int row = cc >> 3;
            const int k8  = cc & 7;
            const __nv_bfloat16* g = srcs[t] + (size_t)row * K + kb + (k8 << 3);
            const u32 d = sb + t * TILE_B + row * 128 + (((u32)k8 ^ ((u32)row & 7)) << 4);
            asm volatile("cp.async.cg.shared.global [%0], [%1], 16;" :: "r"(d), "l"(g));
        }
        asm volatile("cp.async.commit_group;" ::: "memory");
    };

    load_chunk(0, 0);

    for (int c = 0; c < nch; ++c) {
        if (c + 1 < nch) {
            load_chunk(c + 1, (c + 1) & 1);
            asm volatile("cp.async.wait_group 1;" ::: "memory");
        } else {
            asm volatile("cp.async.wait_group 0;" ::: "memory");
        }
        __syncthreads();

        const u32 sA_h = sbase + (c & 1) * STAGE_B;
        const u32 sA_l = sA_h + TILE_B;
        const u32 sB_h = sA_h + 2 * TILE_B;
        const u32 sB_l = sA_h + 3 * TILE_B;

#pragma unroll
        for (int ks = 0; ks < 4; ++ks) {
            const u32 kb = ks << 4;
            u32 ah[4][4], al[4][4], bh[2][4], bl[2][4];
#pragma unroll
            for (int mt = 0; mt < 4; ++mt) {
                ldsm4(ah[mt], swz(sA_h, wm + mt * 16 + a_row, kb + a_k));
                ldsm4(al[mt], swz(sA_l, wm + mt * 16 + a_row, kb + a_k));
            }
#pragma unroll
            for (int np = 0; np < 2; ++np) {
                ldsm4(bh[np], swz(sB_h, wn + np * 16 + b_row, kb + b_k));
                ldsm4(bl[np], swz(sB_l, wn + np * 16 + b_row, kb + b_k));
            }
#pragma unroll
            for (int mt = 0; mt < 4; ++mt)
#pragma unroll
                for (int nt = 0; nt < 4; ++nt) {
                    const u32* bhp = &bh[nt >> 1][(nt & 1) * 2];
                    const u32* blp = &bl[nt >> 1][(nt & 1) * 2];
                    mma_bf16(acc[mt][nt], ah[mt], bhp);
                    mma_bf16(acc[mt][nt], ah[mt], blp);
                    mma_bf16(acc[mt][nt], al[mt], bhp);
                }
        }
        __syncthreads();
    }

    // ---- epilogue ----
    const int g  = lane >> 2;
    const int tg = lane & 3;
#pragma unroll
    for (int mt = 0; mt < 4; ++mt)
#pragma unroll
        for (int nt = 0; nt < 4; ++nt) {
            const int cc = n0 + wn + nt * 8 + tg * 2;
#pragma unroll
            for (int h = 0; h < 2; ++h) {
                const int r = m0 + wm + mt * 16 + g + h * 8;
                float v0 = acc[mt][nt][h * 2 + 0];
                float v1 = acc[mt][nt][h * 2 + 1];
                if (bias) { v0 += bias[cc]; v1 += bias[cc + 1]; }
                if (RELU) { v0 = fmaxf(v0, 0.f); v1 = fmaxf(v1, 0.f); }
                if (WF32)
                    *(float2*)(C + (size_t)r * ldc + cc) = make_float2(v0, v1);
                if (WSPLIT) {
                    __nv_bfloat16 h0 = __float2bfloat16(v0);
                    __nv_bfloat16 h1 = __float2bfloat16(v1);
                    *(__nv_bfloat162*)(Chi + (size_t)r * ldcs + cc) = __halves2bfloat162(h0, h1);
                    *(__nv_bfloat162*)(Clo + (size_t)r * ldcs + cc) = __halves2bfloat162(
                        __float2bfloat16(v0 - __bfloat162float(h0)),
                        __float2bfloat16(v1 - __bfloat162float(h1)));
                }
            }
        }
}

// ======================================================================
// row softmax over 8192 cols (with 1/sqrt(512) folded in) -> bf16 split
// ======================================================================
__global__ __launch_bounds__(256)
void softmax_split(const float* __restrict__ S,
                   __nv_bfloat16* __restrict__ Ahi, __nv_bfloat16* __restrict__ Alo)
{
    __shared__ float red[8];
    const int t = threadIdx.x;
    const int w = t >> 5, lane = t & 31;
    const size_t row = blockIdx.x;
    const float scale = 0.044194173824159216f;
    const float* s = S + row * NH;

    float x[32];
    float mx = -1e30f;
#pragma unroll
    for (int i = 0; i < 8; ++i) {
        float4 v = *(const float4*)(s + ((size_t)(i * 256 + t) << 2));
        x[i * 4 + 0] = v.x * scale; x[i * 4 + 1] = v.y * scale;
        x[i * 4 + 2] = v.z * scale; x[i * 4 + 3] = v.w * scale;
        mx = fmaxf(mx, fmaxf(fmaxf(x[i * 4], x[i * 4 + 1]), fmaxf(x[i * 4 + 2], x[i * 4 + 3])));
    }
#pragma unroll
    for (int o = 16; o; o >>= 1) mx = fmaxf(mx, __shfl_xor_sync(0xFFFFFFFFu, mx, o));
    if (lane == 0) red[w] = mx;
    __syncthreads();
    mx = red[0];
#pragma unroll
    for (int i = 1; i < 8; ++i) mx = fmaxf(mx, red[i]);

    float sum = 0.f;
#pragma unroll
    for (int j = 0; j < 32; ++j) { x[j] = __expf(x[j] - mx); sum += x[j]; }
#pragma unroll
    for (int o = 16; o; o >>= 1) sum += __shfl_xor_sync(0xFFFFFFFFu, sum, o);
    __syncthreads();
    if (lane == 0) red[w] = sum;
    __syncthreads();
    sum = 0.f;
#pragma unroll
    for (int i = 0; i < 8; ++i) sum += red[i];
    const float inv = 1.f / sum;

#pragma unroll
    for (int i = 0; i < 8; ++i) {
        const size_t base = row * NH + ((size_t)(i * 256 + t) << 2);
        float p0 = x[i * 4] * inv, p1 = x[i * 4 + 1] * inv;
        float p2 = x[i * 4 + 2] * inv, p3 = x[i * 4 + 3] * inv;
        __nv_bfloat16 h0 = __float2bfloat16(p0), h1 = __float2bfloat16(p1);
        __nv_bfloat16 h2 = __float2bfloat16(p2), h3 = __float2bfloat16(p3);
        *(__nv_bfloat162*)(Ahi + base)     = __halves2bfloat162(h0, h1);
        *(__nv_bfloat162*)(Ahi + base + 2) = __halves2bfloat162(h2, h3);
        *(__nv_bfloat162*)(Alo + base)     = __halves2bfloat162(
            __float2bfloat16(p0 - __bfloat162float(h0)), __float2bfloat16(p1 - __bfloat162float(h1)));
        *(__nv_bfloat162*)(Alo + base + 2) = __halves2bfloat162(
            __float2bfloat16(p2 - __bfloat162float(h2)), __float2bfloat16(p3 - __bfloat162float(h3)));
    }
}

// fp32 -> (bf16 hi, bf16 lo) split, row-major; 4 elems/thread; n % 1024 == 0
__global__ __launch_bounds__(256)
void split_rm(const float* __restrict__ X,
              __nv_bfloat16* __restrict__ hi, __nv_bfloat16* __restrict__ lo)
{
    const size_t i = ((size_t)blockIdx.x * 256 + threadIdx.x) << 2;
    float4 v = *(const float4*)(X + i);
    __nv_bfloat16 h0 = __float2bfloat16(v.x), h1 = __float2bfloat16(v.y);
    __nv_bfloat16 h2 = __float2bfloat16(v.z), h3 = __float2bfloat16(v.w);
    *(__nv_bfloat162*)(hi + i)     = __halves2bfloat162(h0, h1);
    *(__nv_bfloat162*)(hi + i + 2) = __halves2bfloat162(h2, h3);
    *(__nv_bfloat162*)(lo + i)     = __halves2bfloat162(
        __float2bfloat16(v.x - __bfloat162float(h0)), __float2bfloat16(v.y - __bfloat162float(h1)));
    *(__nv_bfloat162*)(lo + i + 2) = __halves2bfloat162(
        __float2bfloat16(v.z - __bfloat162float(h2)), __float2bfloat16(v.w - __bfloat162float(h3)));
}

// hist [NH][FD] -> transposed splits [FD][NH]
__global__ void splitT(const float* __restrict__ X,
                       __nv_bfloat16* __restrict__ hi, __nv_bfloat16* __restrict__ lo)
{
    __shared__ float tile[32][33];
    const int d0 = blockIdx.x * 32, m0 = blockIdx.y * 32;
    const int tx = threadIdx.x, ty = threadIdx.y;   // (32, 8)
#pragma unroll
    for (int i = 0; i < 32; i += 8)
        tile[ty + i][tx] = X[(size_t)(m0 + ty + i) * FD + d0 + tx];  // tile[m][d]
    __syncthreads();
#pragma unroll
    for (int i = 0; i < 32; i += 8) {
        const float v = tile[tx][ty + i];           // value at (m0+tx, d0+ty+i)
        const size_t o = (size_t)(d0 + ty + i) * NH + m0 + tx;
        __nv_bfloat16 h = __float2bfloat16(v);
        hi[o] = h;
        lo[o] = __float2bfloat16(v - __bfloat162float(h));
    }
}

// ======================================================================
extern "C" void kernel_launch(void* const* d_in, const int* in_sizes, int n_in,
                              void* d_out, int out_size)
{
    const float* cur  = (const float*)d_in[0];   // [4096, 512]
    const float* hist = (const float*)d_in[1];   // [8192, 512]
    const float* W1   = (const float*)d_in[2];   // [3, 128, 512]
    const float* b1   = (const float*)d_in[3];   // [3, 128]
    const float* W2   = (const float*)d_in[4];   // [3, 512, 128]
    const float* b2   = (const float*)d_in[5];   // [3, 512]
    const float* Wf   = (const float*)d_in[6];   // [512, 1536]
    const float* bf   = (const float*)d_in[7];   // [512]
    float* out = (float*)d_out;                  // [4096, 512]

    __nv_bfloat16 *Xhi, *Xlo, *Hhi, *Hlo, *Phi, *Plo, *Thi, *Tlo;
    __nv_bfloat16 *AThi, *ATlo, *Ohi, *Olo, *W1hi, *W1lo, *W2hi, *W2lo, *Wfhi, *Wflo;
    float* S;
    cudaGetSymbolAddress((void**)&Xhi, g_Xhi);   cudaGetSymbolAddress((void**)&Xlo, g_Xlo);
    cudaGetSymbolAddress((void**)&Hhi, g_Hhi);   cudaGetSymbolAddress((void**)&Hlo, g_Hlo);
    cudaGetSymbolAddress((void**)&Phi, g_Phi);   cudaGetSymbolAddress((void**)&Plo, g_Plo);
    cudaGetSymbolAddress((void**)&Thi, g_Thi);   cudaGetSymbolAddress((void**)&Tlo, g_Tlo);
    cudaGetSymbolAddress((void**)&AThi, g_AThi); cudaGetSymbolAddress((void**)&ATlo, g_ATlo);
    cudaGetSymbolAddress((void**)&Ohi, g_Ohi);   cudaGetSymbolAddress((void**)&Olo, g_Olo);
    cudaGetSymbolAddress((void**)&W1hi, g_W1hi); cudaGetSymbolAddress((void**)&W1lo, g_W1lo);
    cudaGetSymbolAddress((void**)&W2hi, g_W2hi); cudaGetSymbolAddress((void**)&W2lo, g_W2lo);
    cudaGetSymbolAddress((void**)&Wfhi, g_Wfhi); cudaGetSymbolAddress((void**)&Wflo, g_Wflo);
    cudaGetSymbolAddress((void**)&S, g_S);

    cudaFuncSetAttribute(mm128<true,  false, true >, cudaFuncAttributeMaxDynamicSharedMemorySize, GSMEM);
    cudaFuncSetAttribute(mm128<false, false, true >, cudaFuncAttributeMaxDynamicSharedMemorySize, GSMEM);
    cudaFuncSetAttribute(mm128<false, true,  false>, cudaFuncAttributeMaxDynamicSharedMemorySize, GSMEM);

    // ---- input / weight splits ----
    split_rm<<<(NC * FD) / 1024, 256>>>(cur,  Xhi,              Xlo);
    split_rm<<<(NH * FD) / 1024, 256>>>(hist, Xhi + (size_t)NC * FD, Xlo + (size_t)NC * FD);
    split_rm<<<(NL * RD * FD) / 1024, 256>>>(W1, W1hi, W1lo);
    split_rm<<<(NL * FD * RD) / 1024, 256>>>(W2, W2hi, W2lo);
    split_rm<<<(FD * NL * FD) / 1024, 256>>>(Wf, Wfhi, Wflo);
    splitT<<<dim3(FD / 32, NH / 32), dim3(32, 8)>>>(hist, Thi, Tlo);

    for (int l = 0; l < NL; ++l) {
        const size_t w1o = (size_t)l * RD * FD;
        const size_t w2o = (size_t)l * FD * RD;

        // H = relu(X @ W1^T + b1)   [12288,128]
        mm128<true, false, true><<<dim3(RD / 128, NT / 128), 256, GSMEM>>>(
            Xhi, Xlo, W1hi + w1o, W1lo + w1o, b1 + (size_t)l * RD,
            nullptr, 0, Hhi, Hlo, RD, FD);

        // P = H @ W2^T + b2         [12288,512]
        mm128<false, false, true><<<dim3(FD / 128, NT / 128), 256, GSMEM>>>(
            Hhi, Hlo, W2hi + w2o, W2lo + w2o, b2 + (size_t)l * FD,
            nullptr, 0, Phi, Plo, FD, RD);

        // S = Pc @ Ph^T             [4096,8192]
        mm128<false, true, false><<<dim3(NH / 128, NC / 128), 256, GSMEM>>>(
            Phi, Plo, Phi + (size_t)NC * FD, Plo + (size_t)NC * FD, nullptr,
            S, NH, nullptr, nullptr, 0, FD);

        // A = softmax(S * scale) -> bf16 splits
        softmax_split<<<NC, 256>>>(S, AThi, ATlo);

        // O_l = A @ hist            [4096,512] into concat cols [l*512, (l+1)*512)
        mm128<false, false, true><<<dim3(FD / 128, NC / 128), 256, GSMEM>>>(
            AThi, ATlo, Thi, Tlo, nullptr,
            nullptr, 0, Ohi + (size_t)l * FD, Olo + (size_t)l * FD, NL * FD, NH);
    }

    // out = concat @ Wf^T + bf      [4096,512]
    mm128<false, true, false><<<dim3(FD / 128, NC / 128), 256, GSMEM>>>(
        Ohi, Olo, Wfhi, Wflo, bf, out, FD, nullptr, nullptr, 0, NL * FD);
}

// round 6
// speedup vs baseline: 12.2498x; 2.1098x over previous
#include <cuda_runtime.h>
#include <cuda_bf16.h>
#include <cuda_fp16.h>

#define NC 4096
#define NH 8192
#define NT 12288
#define FD 512
#define RD 128
#define NL 3

typedef unsigned long long u64;
typedef unsigned int u32;

#define KC 64                     // k elements per chunk
#define TILE_B 16384              // one operand tile: 128 rows x 64 elems x 2B = 16KB
#define GSMEM_B (2 * 4 * TILE_B)  // bf16-3 kernel: 2 stages x (Ahi,Alo,Bhi,Blo) = 128KB
#define GSMEM_H (3 * 2 * TILE_B)  // fp16-1 kernel: 3 stages x (A,B) = 96KB

// ---------------- helpers ----------------
__device__ __forceinline__ u32 smem_u32(const void* p) {
    u32 a;
    asm("{ .reg .u64 t; cvta.to.shared.u64 t, %1; cvt.u32.u64 %0, t; }" : "=r"(a) : "l"(p));
    return a;
}
__device__ __forceinline__ void ldsm4(u32* r, u32 addr) {
    asm volatile("ldmatrix.sync.aligned.m8n8.x4.shared.b16 {%0,%1,%2,%3}, [%4];"
                 : "=r"(r[0]), "=r"(r[1]), "=r"(r[2]), "=r"(r[3]) : "r"(addr));
}
__device__ __forceinline__ void mma_bf16(float* c, const u32* a, const u32* b) {
    asm volatile("mma.sync.aligned.m16n8k16.row.col.f32.bf16.bf16.f32 "
                 "{%0,%1,%2,%3}, {%4,%5,%6,%7}, {%8,%9}, {%0,%1,%2,%3};"
                 : "+f"(c[0]), "+f"(c[1]), "+f"(c[2]), "+f"(c[3])
                 : "r"(a[0]), "r"(a[1]), "r"(a[2]), "r"(a[3]), "r"(b[0]), "r"(b[1]));
}
__device__ __forceinline__ void mma_f16(float* c, const u32* a, const u32* b) {
    asm volatile("mma.sync.aligned.m16n8k16.row.col.f32.f16.f16.f32 "
                 "{%0,%1,%2,%3}, {%4,%5,%6,%7}, {%8,%9}, {%0,%1,%2,%3};"
                 : "+f"(c[0]), "+f"(c[1]), "+f"(c[2]), "+f"(c[3])
                 : "r"(a[0]), "r"(a[1]), "r"(a[2]), "r"(a[3]), "r"(b[0]), "r"(b[1]));
}
// swizzled smem byte address for (row, k) in a [128][64] 16-bit tile (k multiple of 8)
__device__ __forceinline__ u32 swz(u32 base, u32 row, u32 k) {
    return base + row * 128 + ((((k >> 3) ^ (row & 7)) & 7) << 4);
}

// ---------------- scratch (no allocation APIs anywhere) ----------------
__device__ __align__(128) __nv_bfloat16 g_Xhi[(size_t)NT * FD],  g_Xlo[(size_t)NT * FD];
__device__ __align__(128) __nv_bfloat16 g_Hhi[(size_t)NT * RD],  g_Hlo[(size_t)NT * RD];
__device__ __align__(128) __half        g_Pf [(size_t)NT * FD];          // projections, fp16
__device__ __align__(128) __half        g_Tf [(size_t)FD * NH];          // hist^T, fp16
__device__ __align__(128) float         g_S  [(size_t)NC * NH];
__device__ __align__(128) __half        g_Af [(size_t)NC * NH];          // softmax probs, fp16
__device__ __align__(128) __nv_bfloat16 g_Ohi[(size_t)NC * NL * FD], g_Olo[(size_t)NC * NL * FD];
__device__ __align__(128) __nv_bfloat16 g_W1hi[(size_t)NL * RD * FD], g_W1lo[(size_t)NL * RD * FD];
__device__ __align__(128) __nv_bfloat16 g_W2hi[(size_t)NL * FD * RD], g_W2lo[(size_t)NL * FD * RD];
__device__ __align__(128) __nv_bfloat16 g_Wfhi[(size_t)FD * NL * FD], g_Wflo[(size_t)FD * NL * FD];

// ======================================================================
// Split-bf16 HMMA GEMM (3 products): C[M,N] = act(A@B^T + bias)
// OM: 0 = f32 C, 1 = bf16 hi/lo split, 2 = fp16 single
// CTA 128x128, Kc=64, 2-stage cp.async, 256 threads, warp tile 64x32.
// ======================================================================
template<bool RELU, int OM>
__global__ __launch_bounds__(256, 1)
void mm128b(const __nv_bfloat16* __restrict__ Ahi, const __nv_bfloat16* __restrict__ Alo,
            const __nv_bfloat16* __restrict__ Bhi, const __nv_bfloat16* __restrict__ Blo,
            const float* __restrict__ bias,
            float* __restrict__ C, int ldc,
            __nv_bfloat16* __restrict__ Chi, __nv_bfloat16* __restrict__ Clo,
            __half* __restrict__ Ch, int ldcs,
            int K)
{
    extern __shared__ __align__(1024) char smem[];
    const int tid  = threadIdx.x;
    const int wid  = tid >> 5;
    const int lane = tid & 31;
    const int m0 = blockIdx.y * 128;
    const int n0 = blockIdx.x * 128;
    const int wm = (wid & 1) * 64;
    const int wn = (wid >> 1) * 32;

    const u32 sbase = smem_u32(smem);
    const __nv_bfloat16* srcs[4] = { Ahi + (size_t)m0 * K, Alo + (size_t)m0 * K,
                                     Bhi + (size_t)n0 * K, Blo + (size_t)n0 * K };

    float acc[4][4][4];
#pragma unroll
    for (int i = 0; i < 4; ++i)
#pragma unroll
        for (int j = 0; j < 4; ++j)
#pragma unroll
            for (int h = 0; h < 4; ++h) acc[i][j][h] = 0.f;

    const u32 a_row = lane & 15;
    const u32 a_k   = (lane >> 4) << 3;
    const u32 b_row = ((lane >> 4) << 3) + (lane & 7);
    const u32 b_k   = ((lane >> 3) & 1) << 3;

    const int nch = K / KC;

    auto load_chunk = [&](int c, int buf) {
        const int kb = c * KC;
        const u32 sb = sbase + buf * 4 * TILE_B;
#pragma unroll
        for (int i = 0; i < 16; ++i) {
            const int t  = i >> 2;
            const int cc = ((i & 3) << 8) + tid;
            const int row = cc >> 3;
            const int k8  = cc & 7;
            const __nv_bfloat16* g = srcs[t] + (size_t)row * K + kb + (k8 << 3);
            const u32 d = sb + t * TILE_B + row * 128 + (((u32)k8 ^ ((u32)row & 7)) << 4);
            asm volatile("cp.async.cg.shared.global [%0], [%1], 16;" :: "r"(d), "l"(g));
        }
        asm volatile("cp.async.commit_group;" ::: "memory");
    };

    load_chunk(0, 0);

    for (int c = 0; c < nch; ++c) {
        if (c + 1 < nch) {
            load_chunk(c + 1, (c + 1) & 1);
            asm volatile("cp.async.wait_group 1;" ::: "memory");
        } else {
            asm volatile("cp.async.wait_group 0;" ::: "memory");
        }
        __syncthreads();

        const u32 sA_h = sbase + (c & 1) * 4 * TILE_B;
        const u32 sA_l = sA_h + TILE_B;
        const u32 sB_h = sA_h + 2 * TILE_B;
        const u32 sB_l = sA_h + 3 * TILE_B;

#pragma unroll
        for (int ks = 0; ks < 4; ++ks) {
            const u32 kb = ks << 4;
            u32 ah[4][4], al[4][4], bh[2][4], bl[2][4];
#pragma unroll
            for (int mt = 0; mt < 4; ++mt) {
                ldsm4(ah[mt], swz(sA_h, wm + mt * 16 + a_row, kb + a_k));
                ldsm4(al[mt], swz(sA_l, wm + mt * 16 + a_row, kb + a_k));
            }
#pragma unroll
            for (int np = 0; np < 2; ++np) {
                ldsm4(bh[np], swz(sB_h, wn + np * 16 + b_row, kb + b_k));
                ldsm4(bl[np], swz(sB_l, wn + np * 16 + b_row, kb + b_k));
            }
#pragma unroll
            for (int mt = 0; mt < 4; ++mt)
#pragma unroll
                for (int nt = 0; nt < 4; ++nt) {
                    const u32* bhp = &bh[nt >> 1][(nt & 1) * 2];
                    const u32* blp = &bl[nt >> 1][(nt & 1) * 2];
                    mma_bf16(acc[mt][nt], ah[mt], bhp);
                    mma_bf16(acc[mt][nt], ah[mt], blp);
                    mma_bf16(acc[mt][nt], al[mt], bhp);
                }
        }
        __syncthreads();
    }

    const int g  = lane >> 2;
    const int tg = lane & 3;
#pragma unroll
    for (int mt = 0; mt < 4; ++mt)
#pragma unroll
        for (int nt = 0; nt < 4; ++nt) {
            const int cc = n0 + wn + nt * 8 + tg * 2;
#pragma unroll
            for (int h = 0; h < 2; ++h) {
                const int r = m0 + wm + mt * 16 + g + h * 8;
                float v0 = acc[mt][nt][h * 2 + 0];
                float v1 = acc[mt][nt][h * 2 + 1];
                if (bias) { v0 += bias[cc]; v1 += bias[cc + 1]; }
                if (RELU) { v0 = fmaxf(v0, 0.f); v1 = fmaxf(v1, 0.f); }
                if (OM == 0)
                    *(float2*)(C + (size_t)r * ldc + cc) = make_float2(v0, v1);
                if (OM == 1) {
                    __nv_bfloat16 h0 = __float2bfloat16(v0);
                    __nv_bfloat16 h1 = __float2bfloat16(v1);
                    *(__nv_bfloat162*)(Chi + (size_t)r * ldcs + cc) = __halves2bfloat162(h0, h1);
                    *(__nv_bfloat162*)(Clo + (size_t)r * ldcs + cc) = __halves2bfloat162(
                        __float2bfloat16(v0 - __bfloat162float(h0)),
                        __float2bfloat16(v1 - __bfloat162float(h1)));
                }
                if (OM == 2)
                    *(__half2*)(Ch + (size_t)r * ldcs + cc) =
                        __halves2half2(__float2half_rn(v0), __float2half_rn(v1));
            }
        }
}

// ======================================================================
// fp16 single-product HMMA GEMM: C[M,N] = A[M,K] @ B[N,K]^T
// OM: 0 = f32 C, 1 = bf16 hi/lo split
// CTA 128x128, Kc=64, 3-stage cp.async, 256 threads, 2 CTAs/SM.
// ======================================================================
template<int OM>
__global__ __launch_bounds__(256, 2)
void mmh(const __half* __restrict__ A, const __half* __restrict__ B,
         float* __restrict__ C, int ldc,
         __nv_bfloat16* __restrict__ Chi, __nv_bfloat16* __restrict__ Clo, int ldcs,
         int K)
{
    extern __shared__ __align__(1024) char smem[];
    const int tid  = threadIdx.x;
    const int wid  = tid >> 5;
    const int lane = tid & 31;
    const int m0 = blockIdx.y * 128;
    const int n0 = blockIdx.x * 128;
    const int wm = (wid & 1) * 64;
    const int wn = (wid >> 1) * 32;

    const u32 sbase = smem_u32(smem);
    const __half* srcs[2] = { A + (size_t)m0 * K, B + (size_t)n0 * K };

    float acc[4][4][4];
#pragma unroll
    for (int i = 0; i < 4; ++i)
#pragma unroll
        for (int j = 0; j < 4; ++j)
#pragma unroll
            for (int h = 0; h < 4; ++h) acc[i][j][h] = 0.f;

    const u32 a_row = lane & 15;
    const u32 a_k   = (lane >> 4) << 3;
    const u32 b_row = ((lane >> 4) << 3) + (lane & 7);
    const u32 b_k   = ((lane >> 3) & 1) << 3;

    const int nch = K / KC;

    auto load_chunk = [&](int c) {
        const int kb = c * KC;
        const u32 sb = sbase + (c % 3) * 2 * TILE_B;
#pragma unroll
        for (int i = 0; i < 8; ++i) {
            const int t  = i >> 2;
            const int cc = ((i & 3) << 8) + tid;
            const int row = cc >> 3;
            const int k8  = cc & 7;
            const __half* g = srcs[t] + (size_t)row * K + kb + (k8 << 3);
            const u32 d = sb + t * TILE_B + row * 128 + (((u32)k8 ^ ((u32)row & 7)) << 4);
            asm volatile("cp.async.cg.shared.global [%0], [%1], 16;" :: "r"(d), "l"(g));
        }
        asm volatile("cp.async.commit_group;" ::: "memory");
    };

    load_chunk(0);
    if (nch > 1) load_chunk(1);

    for (int c = 0; c < nch; ++c) {
        if (c + 1 < nch) { asm volatile("cp.async.wait_group 1;" ::: "memory"); }
        else             { asm volatile("cp.async.wait_group 0;" ::: "memory"); }
        __syncthreads();                       // buf c ready; all done computing c-1
        if (c + 2 < nch) load_chunk(c + 2);    // overwrites buf (c-1)%3: safe after sync

        const u32 sA = sbase + (c % 3) * 2 * TILE_B;
        const u32 sB = sA + TILE_B;

#pragma unroll
        for (int ks = 0; ks < 4; ++ks) {
            const u32 kb = ks << 4;
            u32 ah[4][4], bh[2][4];
#pragma unroll
            for (int mt = 0; mt < 4; ++mt)
                ldsm4(ah[mt], swz(sA, wm + mt * 16 + a_row, kb + a_k));
#pragma unroll
            for (int np = 0; np < 2; ++np)
                ldsm4(bh[np], swz(sB, wn + np * 16 + b_row, kb + b_k));
#pragma unroll
            for (int mt = 0; mt < 4; ++mt)
#pragma unroll
                for (int nt = 0; nt < 4; ++nt)
                    mma_f16(acc[mt][nt], ah[mt], &bh[nt >> 1][(nt & 1) * 2]);
        }
    }

    const int g  = lane >> 2;
    const int tg = lane & 3;
#pragma unroll
    for (int mt = 0; mt < 4; ++mt)
#pragma unroll
        for (int nt = 0; nt < 4; ++nt) {
            const int cc = n0 + wn + nt * 8 + tg * 2;
#pragma unroll
            for (int h = 0; h < 2; ++h) {
                const int r = m0 + wm + mt * 16 + g + h * 8;
                float v0 = acc[mt][nt][h * 2 + 0];
                float v1 = acc[mt][nt][h * 2 + 1];
                if (OM == 0)
                    *(float2*)(C + (size_t)r * ldc + cc) = make_float2(v0, v1);
                if (OM == 1) {
                    __nv_bfloat16 h0 = __float2bfloat16(v0);
                    __nv_bfloat16 h1 = __float2bfloat16(v1);
                    *(__nv_bfloat162*)(Chi + (size_t)r * ldcs + cc) = __halves2bfloat162(h0, h1);
                    *(__nv_bfloat162*)(Clo + (size_t)r * ldcs + cc) = __halves2bfloat162(
                        __float2bfloat16(v0 - __bfloat162float(h0)),
                        __float2bfloat16(v1 - __bfloat162float(h1)));
                }
            }
        }
}

// ======================================================================
// row softmax over 8192 cols (1/sqrt(512) folded in) -> fp16 probs
// ======================================================================
__global__ __launch_bounds__(256)
void softmax_h(const float* __restrict__ S, __half* __restrict__ Af)
{
    __shared__ float red[8];
    const int t = threadIdx.x;
    const int w = t >> 5, lane = t & 31;
    const size_t row = blockIdx.x;
    const float scale = 0.044194173824159216f;
    const float* s = S + row * NH;

    float x[32];
    float mx = -1e30f;
#pragma unroll
    for (int i = 0; i < 8; ++i) {
        float4 v = *(const float4*)(s + ((size_t)(i * 256 + t) << 2));
        x[i * 4 + 0] = v.x * scale; x[i * 4 + 1] = v.y * scale;
        x[i * 4 + 2] = v.z * scale; x[i * 4 + 3] = v.w * scale;
        mx = fmaxf(mx, fmaxf(fmaxf(x[i * 4], x[i * 4 + 1]), fmaxf(x[i * 4 + 2], x[i * 4 + 3])));
    }
#pragma unroll
    for (int o = 16; o; o >>= 1) mx = fmaxf(mx, __shfl_xor_sync(0xFFFFFFFFu, mx, o));
    if (lane == 0) red[w] = mx;
    __syncthreads();
    mx = red[0];
#pragma unroll
    for (int i = 1; i < 8; ++i) mx = fmaxf(mx, red[i]);

    float sum = 0.f;
#pragma unroll
    for (int j = 0; j < 32; ++j) { x[j] = __expf(x[j] - mx); sum += x[j]; }
#pragma unroll
    for (int o = 16; o; o >>= 1) sum += __shfl_xor_sync(0xFFFFFFFFu, sum, o);
    __syncthreads();
    if (lane == 0) red[w] = sum;
    __syncthreads();
    sum = 0.f;
#pragma unroll
    for (int i = 0; i < 8; ++i) sum += red[i];
    const float inv = 1.f / sum;

#pragma unroll
    for (int i = 0; i < 8; ++i) {
        const size_t base = row * NH + ((size_t)(i * 256 + t) << 2);
        *(__half2*)(Af + base)     = __halves2half2(__float2half_rn(x[i * 4] * inv),
                                                    __float2half_rn(x[i * 4 + 1] * inv));
        *(__half2*)(Af + base + 2) = __halves2half2(__float2half_rn(x[i * 4 + 2] * inv),
                                                    __float2half_rn(x[i * 4 + 3] * inv));
    }
}

// fp32 -> (bf16 hi, bf16 lo) split, row-major; 4 elems/thread; n % 1024 == 0
__global__ __launch_bounds__(256)
void split_rm(const float* __restrict__ X,
              __nv_bfloat16* __restrict__ hi, __nv_bfloat16* __restrict__ lo)
{
    const size_t i = ((size_t)blockIdx.x * 256 + threadIdx.x) << 2;
    float4 v = *(const float4*)(X + i);
    __nv_bfloat16 h0 = __float2bfloat16(v.x), h1 = __float2bfloat16(v.y);
    __nv_bfloat16 h2 = __float2bfloat16(v.z), h3 = __float2bfloat16(v.w);
    *(__nv_bfloat162*)(hi + i)     = __halves2bfloat162(h0, h1);
    *(__nv_bfloat162*)(hi + i + 2) = __halves2bfloat162(h2, h3);
    *(__nv_bfloat162*)(lo + i)     = __halves2bfloat162(
        __float2bfloat16(v.x - __bfloat162float(h0)), __float2bfloat16(v.y - __bfloat162float(h1)));
    *(__nv_bfloat162*)(lo + i + 2) = __halves2bfloat162(
        __float2bfloat16(v.z - __bfloat162float(h2)), __float2bfloat16(v.w - __bfloat162float(h3)));
}

// hist [NH][FD] -> transposed fp16 [FD][NH]
__global__ void splitTh(const float* __restrict__ X, __half* __restrict__ T)
{
    __shared__ float tile[32][33];
    const int d0 = blockIdx.x * 32, m0 = blockIdx.y * 32;
    const int tx = threadIdx.x, ty = threadIdx.y;   // (32, 8)
#pragma unroll
    for (int i = 0; i < 32; i += 8)
        tile[ty + i][tx] = X[(size_t)(m0 + ty + i) * FD + d0 + tx];
    __syncthreads();
#pragma unroll
    for (int i = 0; i < 32; i += 8)
        T[(size_t)(d0 + ty + i) * NH + m0 + tx] = __float2half_rn(tile[tx][ty + i]);
}

// ======================================================================
extern "C" void kernel_launch(void* const* d_in, const int* in_sizes, int n_in,
                              void* d_out, int out_size)
{
    const float* cur  = (const float*)d_in[0];
    const float* hist = (const float*)d_in[1];
    const float* W1   = (const float*)d_in[2];
    const float* b1   = (const float*)d_in[3];
    const float* W2   = (const float*)d_in[4];
    const float* b2   = (const float*)d_in[5];
    const float* Wf   = (const float*)d_in[6];
    const float* bf   = (const float*)d_in[7];
    float* out = (float*)d_out;

    __nv_bfloat16 *Xhi, *Xlo, *Hhi, *Hlo, *Ohi, *Olo;
    __nv_bfloat16 *W1hi, *W1lo, *W2hi, *W2lo, *Wfhi, *Wflo;
    __half *Pf, *Tf, *Af;
    float* S;
    cudaGetSymbolAddress((void**)&Xhi, g_Xhi);   cudaGetSymbolAddress((void**)&Xlo, g_Xlo);
    cudaGetSymbolAddress((void**)&Hhi, g_Hhi);   cudaGetSymbolAddress((void**)&Hlo, g_Hlo);
    cudaGetSymbolAddress((void**)&Pf,  g_Pf);    cudaGetSymbolAddress((void**)&Tf,  g_Tf);
    cudaGetSymbolAddress((void**)&Af,  g_Af);    cudaGetSymbolAddress((void**)&S,   g_S);
    cudaGetSymbolAddress((void**)&Ohi, g_Ohi);   cudaGetSymbolAddress((void**)&Olo, g_Olo);
    cudaGetSymbolAddress((void**)&W1hi, g_W1hi); cudaGetSymbolAddress((void**)&W1lo, g_W1lo);
    cudaGetSymbolAddress((void**)&W2hi, g_W2hi); cudaGetSymbolAddress((void**)&W2lo, g_W2lo);
    cudaGetSymbolAddress((void**)&Wfhi, g_Wfhi); cudaGetSymbolAddress((void**)&Wflo, g_Wflo);

    cudaFuncSetAttribute(mm128b<true,  1>, cudaFuncAttributeMaxDynamicSharedMemorySize, GSMEM_B);
    cudaFuncSetAttribute(mm128b<false, 2>, cudaFuncAttributeMaxDynamicSharedMemorySize, GSMEM_B);
    cudaFuncSetAttribute(mm128b<false, 0>, cudaFuncAttributeMaxDynamicSharedMemorySize, GSMEM_B);
    cudaFuncSetAttribute(mmh<0>, cudaFuncAttributeMaxDynamicSharedMemorySize, GSMEM_H);
    cudaFuncSetAttribute(mmh<1>, cudaFuncAttributeMaxDynamicSharedMemorySize, GSMEM_H);

    // ---- input / weight preprocessing ----
    split_rm<<<(NC * FD) / 1024, 256>>>(cur,  Xhi,                   Xlo);
    split_rm<<<(NH * FD) / 1024, 256>>>(hist, Xhi + (size_t)NC * FD, Xlo + (size_t)NC * FD);
    split_rm<<<(NL * RD * FD) / 1024, 256>>>(W1, W1hi, W1lo);
    split_rm<<<(NL * FD * RD) / 1024, 256>>>(W2, W2hi, W2lo);
    split_rm<<<(FD * NL * FD) / 1024, 256>>>(Wf, Wfhi, Wflo);
    splitTh<<<dim3(FD / 32, NH / 32), dim3(32, 8)>>>(hist, Tf);

    for (int l = 0; l < NL; ++l) {
        const size_t w1o = (size_t)l * RD * FD;
        const size_t w2o = (size_t)l * FD * RD;

        // H = relu(X @ W1^T + b1)   [12288,128]  bf16-3 -> bf16 split
        mm128b<true, 1><<<dim3(RD / 128, NT / 128), 256, GSMEM_B>>>(
            Xhi, Xlo, W1hi + w1o, W1lo + w1o, b1 + (size_t)l * RD,
            nullptr, 0, Hhi, Hlo, nullptr, RD, FD);

        // P = H @ W2^T + b2         [12288,512]  bf16-3 -> fp16
        mm128b<false, 2><<<dim3(FD / 128, NT / 128), 256, GSMEM_B>>>(
            Hhi, Hlo, W2hi + w2o, W2lo + w2o, b2 + (size_t)l * FD,
            nullptr, 0, nullptr, nullptr, Pf, FD, RD);

        // S = Pc @ Ph^T             [4096,8192]  fp16-1 -> f32
        mmh<0><<<dim3(NH / 128, NC / 128), 256, GSMEM_H>>>(
            Pf, Pf + (size_t)NC * FD, S, NH, nullptr, nullptr, 0, FD);

        // A = softmax(S * scale)    fp16 probs
        softmax_h<<<NC, 256>>>(S, Af);

        // O_l = A @ hist            [4096,512]   fp16-1 -> bf16 split (concat layout)
        mmh<1><<<dim3(FD / 128, NC / 128), 256, GSMEM_H>>>(
            Af, Tf, nullptr, 0, Ohi + (size_t)l * FD, Olo + (size_t)l * FD, NL * FD, NH);
    }

    // out = concat @ Wf^T + bf      [4096,512]   bf16-3 -> f32
    mm128b<false, 0><<<dim3(FD / 128, NC / 128), 256, GSMEM_B>>>(
        Ohi, Olo, Wfhi, Wflo, bf, out, FD, nullptr, nullptr, nullptr, 0, NL * FD);
}

// round 7
// speedup vs baseline: 12.4661x; 1.0177x over previous
#include <cuda_runtime.h>
#include <cuda_bf16.h>
#include <cuda_fp16.h>

#define NC 4096
#define NH 8192
#define NT 12288
#define FD 512
#define RD 128
#define NL 3
#define LDA_CAT (NL * NH)     // 24576

typedef unsigned long long u64;
typedef unsigned int u32;

#define KC 64                     // k elements per chunk
#define TILE_B 16384              // 128 rows x 64 elems x 2B
#define GSMEM_B (2 * 4 * TILE_B)  // bf16-3 kernel: 2 stages x 4 tiles = 128KB

static const float SCALE = 0.044194173824159216f;  // 1/sqrt(512)

// ---------------- helpers ----------------
__device__ __forceinline__ u32 smem_u32(const void* p) {
    u32 a;
    asm("{ .reg .u64 t; cvta.to.shared.u64 t, %1; cvt.u32.u64 %0, t; }" : "=r"(a) : "l"(p));
    return a;
}
__device__ __forceinline__ void ldsm4(u32* r, u32 addr) {
    asm volatile("ldmatrix.sync.aligned.m8n8.x4.shared.b16 {%0,%1,%2,%3}, [%4];"
                 : "=r"(r[0]), "=r"(r[1]), "=r"(r[2]), "=r"(r[3]) : "r"(addr));
}
__device__ __forceinline__ void mma_bf16(float* c, const u32* a, const u32* b) {
    asm volatile("mma.sync.aligned.m16n8k16.row.col.f32.bf16.bf16.f32 "
                 "{%0,%1,%2,%3}, {%4,%5,%6,%7}, {%8,%9}, {%0,%1,%2,%3};"
                 : "+f"(c[0]), "+f"(c[1]), "+f"(c[2]), "+f"(c[3])
                 : "r"(a[0]), "r"(a[1]), "r"(a[2]), "r"(a[3]), "r"(b[0]), "r"(b[1]));
}
__device__ __forceinline__ void mma_f16(float* c, const u32* a, const u32* b) {
    asm volatile("mma.sync.aligned.m16n8k16.row.col.f32.f16.f16.f32 "
                 "{%0,%1,%2,%3}, {%4,%5,%6,%7}, {%8,%9}, {%0,%1,%2,%3};"
                 : "+f"(c[0]), "+f"(c[1]), "+f"(c[2]), "+f"(c[3])
                 : "r"(a[0]), "r"(a[1]), "r"(a[2]), "r"(a[3]), "r"(b[0]), "r"(b[1]));
}
// swizzled smem byte addr for (row, k) in a [rows][64] 16-bit tile (k multiple of 8)
__device__ __forceinline__ u32 swz(u32 base, u32 row, u32 k) {
    return base + row * 128 + ((((k >> 3) ^ (row & 7)) & 7) << 4);
}

// ---------------- scratch ----------------
__device__ __align__(128) __nv_bfloat16 g_Xhi[(size_t)NT * FD],  g_Xlo[(size_t)NT * FD];
__device__ __align__(128) __nv_bfloat16 g_W1hi[(size_t)NL * RD * FD], g_W1lo[(size_t)NL * RD * FD];
__device__ __align__(128) __nv_bfloat16 g_Wfhi[(size_t)FD * NL * FD], g_Wflo[(size_t)FD * NL * FD];
__device__ __align__(128) __nv_bfloat16 g_Ghi[(size_t)NL * RD * RD],  g_Glo[(size_t)NL * RD * RD];
__device__ __align__(128) __nv_bfloat16 g_Hhi[(size_t)NT * RD],  g_Hlo[(size_t)NT * RD];
__device__ __align__(128) __half        g_Hhf[(size_t)NH * RD];       // historical H, fp16
__device__ __align__(128) __half        g_Hcf[(size_t)NC * RD];       // Hc' = Hc*G*scale, fp16
__device__ __align__(128) float         g_S  [(size_t)NC * NH];
__device__ __align__(128) __half        g_Af [(size_t)NC * LDA_CAT];  // probs, concat cols
__device__ __align__(128) __half        g_VfT[(size_t)FD * LDA_CAT];  // (V*Wf_l^T)^T blocks
__device__ __align__(128) float         g_v  [NL * RD];
__device__ __align__(128) float         g_cv [NH];

// ======================================================================
// Split-bf16 HMMA GEMM (3 products): C = act(A@B^T + bias)
// OM: 1 = bf16 hi/lo split out, 2 = fp16 out.  Row strides lda/ldb.
// CTA 128x128, Kc=64, 2-stage cp.async, 256 threads, warp tile 64x32.
// ======================================================================
template<bool RELU, int OM>
__global__ __launch_bounds__(256, 1)
void mm128b(const __nv_bfloat16* __restrict__ Ahi, const __nv_bfloat16* __restrict__ Alo,
            const __nv_bfloat16* __restrict__ Bhi, const __nv_bfloat16* __restrict__ Blo,
            int lda, int ldb,
            const float* __restrict__ bias,
            __nv_bfloat16* __restrict__ Chi, __nv_bfloat16* __restrict__ Clo,
            __half* __restrict__ Ch, int ldcs,
            int K)
{
    extern __shared__ __align__(1024) char smem[];
    const int tid  = threadIdx.x;
    const int wid  = tid >> 5;
    const int lane = tid & 31;
    const int m0 = blockIdx.y * 128;
    const int n0 = blockIdx.x * 128;
    const int wm = (wid & 1) * 64;
    const int wn = (wid >> 1) * 32;

    const u32 sbase = smem_u32(smem);
    const __nv_bfloat16* srcs[4] = { Ahi + (size_t)m0 * lda, Alo + (size_t)m0 * lda,
                                     Bhi + (size_t)n0 * ldb, Blo + (size_t)n0 * ldb };
    const int lds[4] = { lda, lda, ldb, ldb };

    float acc[4][4][4];
#pragma unroll
    for (int i = 0; i < 4; ++i)
#pragma unroll
        for (int j = 0; j < 4; ++j)
#pragma unroll
            for (int h = 0; h < 4; ++h) acc[i][j][h] = 0.f;

    const u32 a_row = lane & 15;
    const u32 a_k   = (lane >> 4) << 3;
    const u32 b_row = ((lane >> 4) << 3) + (lane & 7);
    const u32 b_k   = ((lane >> 3) & 1) << 3;

    const int nch = K / KC;

    auto load_chunk = [&](int c, int buf) {
        const int kb = c * KC;
        const u32 sb = sbase + buf * 4 * TILE_B;
#pragma unroll
        for (int i = 0; i < 16; ++i) {
            const int t  = i >> 2;
            const int cc = ((i & 3) << 8) + tid;
            const int row = cc >> 3;
            const int k8  = cc & 7;
            const __nv_bfloat16* g = srcs[t] + (size_t)row * lds[t] + kb + (k8 << 3);
            const u32 d = sb + t * TILE_B + row * 128 + (((u32)k8 ^ ((u32)row & 7)) << 4);
            asm volatile("cp.async.cg.shared.global [%0], [%1], 16;" :: "r"(d), "l"(g));
        }
        asm volatile("cp.async.commit_group;" ::: "memory");
    };

    load_chunk(0, 0);

    for (int c = 0; c < nch; ++c) {
        if (c + 1 < nch) {
            load_chunk(c + 1, (c + 1) & 1);
            asm volatile("cp.async.wait_group 1;" ::: "memory");
        } else {
            asm volatile("cp.async.wait_group 0;" ::: "memory");
        }
        __syncthreads();

        const u32 sA_h = sbase + (c & 1) * 4 * TILE_B;
        const u32 sA_l = sA_h + TILE_B;
        const u32 sB_h = sA_h + 2 * TILE_B;
        const u32 sB_l = sA_h + 3 * TILE_B;

#pragma unroll
        for (int ks = 0; ks < 4; ++ks) {
            const u32 kb = ks << 4;
            u32 ah[4][4], al[4][4], bh[2][4], bl[2][4];
#pragma unroll
            for (int mt = 0; mt < 4; ++mt) {
                ldsm4(ah[mt], swz(sA_h, wm + mt * 16 + a_row, kb + a_k));
                ldsm4(al[mt], swz(sA_l, wm + mt * 16 + a_row, kb + a_k));
            }
#pragma unroll
            for (int np = 0; np < 2; ++np) {
                ldsm4(bh[np], swz(sB_h, wn + np * 16 + b_row, kb + b_k));
                ldsm4(bl[np], swz(sB_l, wn + np * 16 + b_row, kb + b_k));
            }
#pragma unroll
            for (int mt = 0; mt < 4; ++mt)
#pragma unroll
                for (int nt = 0; nt < 4; ++nt) {
                    const u32* bhp = &bh[nt >> 1][(nt & 1) * 2];
                    const u32* blp = &bl[nt >> 1][(nt & 1) * 2];
                    mma_bf16(acc[mt][nt], ah[mt], bhp);
                    mma_bf16(acc[mt][nt], ah[mt], blp);
                    mma_bf16(acc[mt][nt], al[mt], bhp);
                }
        }
        __syncthreads();
    }

    const int g  = lane >> 2;
    const int tg = lane & 3;
#pragma unroll
    for (int mt = 0; mt < 4; ++mt)
#pragma unroll
        for (int nt = 0; nt < 4; ++nt) {
            const int cc = n0 + wn + nt * 8 + tg * 2;
#pragma unroll
            for (int h = 0; h < 2; ++h) {
                const int r = m0 + wm + mt * 16 + g + h * 8;
                float v0 = acc[mt][nt][h * 2 + 0];
                float v1 = acc[mt][nt][h * 2 + 1];
                if (bias) { v0 += bias[cc]; v1 += bias[cc + 1]; }
                if (RELU) { v0 = fmaxf(v0, 0.f); v1 = fmaxf(v1, 0.f); }
                if (OM == 1) {
                    __nv_bfloat16 h0 = __float2bfloat16(v0);
                    __nv_bfloat16 h1 = __float2bfloat16(v1);
                    *(__nv_bfloat162*)(Chi + (size_t)r * ldcs + cc) = __halves2bfloat162(h0, h1);
                    *(__nv_bfloat162*)(Clo + (size_t)r * ldcs + cc) = __halves2bfloat162(
                        __float2bfloat16(v0 - __bfloat162float(h0)),
                        __float2bfloat16(v1 - __bfloat162float(h1)));
                }
                if (OM == 2)
                    *(__half2*)(Ch + (size_t)r * ldcs + cc) =
                        __halves2half2(__float2half_rn(v0), __float2half_rn(v1));
            }
        }
}

// ======================================================================
// fp16 single-product HMMA GEMM: C[M,N] = A@B^T (+ bias), f32 out.
// BM = 128 or 64 (M tile). Packed operands (lda = ldb = K).
// 3-stage cp.async, 256 threads, 2 CTAs/SM.
// ======================================================================
template<int BM>
__global__ __launch_bounds__(256, 2)
void mmh(const __half* __restrict__ A, const __half* __restrict__ B,
         const float* __restrict__ bias,
         float* __restrict__ C, int ldc, int K)
{
    constexpr int MF = BM / 32;              // m fragments per warp (16 rows each)
    constexpr int TILE_A = BM * 128;         // bytes
    constexpr int STAGE = TILE_A + TILE_B;
    constexpr int ITA = (BM * 8) / 256;      // A-load iterations

    extern __shared__ __align__(1024) char smem[];
    const int tid  = threadIdx.x;
    const int wid  = tid >> 5;
    const int lane = tid & 31;
    const int m0 = blockIdx.y * BM;
    const int n0 = blockIdx.x * 128;
    const int wm = (wid & 1) * (BM / 2);
    const int wn = (wid >> 1) * 32;

    const u32 sbase = smem_u32(smem);
    const __half* Asrc = A + (size_t)m0 * K;
    const __half* Bsrc = B + (size_t)n0 * K;

    float acc[MF][4][4];
#pragma unroll
    for (int i = 0; i < MF; ++i)
#pragma unroll
        for (int j = 0; j < 4; ++j)
#pragma unroll
            for (int h = 0; h < 4; ++h) acc[i][j][h] = 0.f;

    const u32 a_row = lane & 15;
    const u32 a_k   = (lane >> 4) << 3;
    const u32 b_row = ((lane >> 4) << 3) + (lane & 7);
    const u32 b_k   = ((lane >> 3) & 1) << 3;

    const int nch = K / KC;

    auto load_chunk = [&](int c) {
        const int kb = c * KC;
        const u32 sb = sbase + (c % 3) * STAGE;
#pragma unroll
        for (int i = 0; i < ITA + 4; ++i) {
            const bool isA = i < ITA;
            const int cc = (isA ? i : i - ITA) * 256 + tid;
            const int row = cc >> 3;
            const int k8  = cc & 7;
            const __half* g = (isA ? Asrc : Bsrc) + (size_t)row * K + kb + (k8 << 3);
            const u32 d = sb + (isA ? 0 : TILE_A) + row * 128
                        + (((u32)k8 ^ ((u32)row & 7)) << 4);
            asm volatile("cp.async.cg.shared.global [%0], [%1], 16;" :: "r"(d), "l"(g));
        }
        asm volatile("cp.async.commit_group;" ::: "memory");
    };

    load_chunk(0);
    if (nch > 1) load_chunk(1);

    for (int c = 0; c < nch; ++c) {
        if (c + 1 < nch) { asm volatile("cp.async.wait_group 1;" ::: "memory"); }
        else             { asm volatile("cp.async.wait_group 0;" ::: "memory"); }
        __syncthreads();
        if (c + 2 < nch) load_chunk(c + 2);

        const u32 sA = sbase + (c % 3) * STAGE;
        const u32 sB = sA + TILE_A;

#pragma unroll
        for (int ks = 0; ks < 4; ++ks) {
            const u32 kb = ks << 4;
            u32 ah[MF][4], bh[2][4];
#pragma unroll
            for (int mt = 0; mt < MF; ++mt)
                ldsm4(ah[mt], swz(sA, wm + mt * 16 + a_row, kb + a_k));
#pragma unroll
            for (int np = 0; np < 2; ++np)
                ldsm4(bh[np], swz(sB, wn + np * 16 + b_row, kb + b_k));
#pragma unroll
            for (int mt = 0; mt < MF; ++mt)
#pragma unroll
                for (int nt = 0; nt < 4; ++nt)
                    mma_f16(acc[mt][nt], ah[mt], &bh[nt >> 1][(nt & 1) * 2]);
        }
    }

    const int g  = lane >> 2;
    const int tg = lane & 3;
#pragma unroll
    for (int mt = 0; mt < MF; ++mt)
#pragma unroll
        for (int nt = 0; nt < 4; ++nt) {
            const int cc = n0 + wn + nt * 8 + tg * 2;
#pragma unroll
            for (int h = 0; h < 2; ++h) {
                const int r = m0 + wm + mt * 16 + g + h * 8;
                float v0 = acc[mt][nt][h * 2 + 0];
                float v1 = acc[mt][nt][h * 2 + 1];
                if (bias) { v0 += bias[cc]; v1 += bias[cc + 1]; }
                *(float2*)(C + (size_t)r * ldc + cc) = make_float2(v0, v1);
            }
        }
}

// ======================================================================
// row softmax over NH cols of S + per-col bias cv; writes fp16 probs
// (scale already folded into S and cv upstream)
// ======================================================================
__global__ __launch_bounds__(256)
void softmax_h(const float* __restrict__ S, const float* __restrict__ cv,
               __half* __restrict__ Af, size_t ldaf)
{
    __shared__ float red[8];
    const int t = threadIdx.x;
    const int w = t >> 5, lane = t & 31;
    const size_t row = blockIdx.x;
    const float* s = S + row * NH;

    float x[32];
    float mx = -1e30f;
#pragma unroll
    for (int i = 0; i < 8; ++i) {
        const size_t o = (size_t)(i * 256 + t) << 2;
        float4 v = *(const float4*)(s + o);
        float4 c = *(const float4*)(cv + o);
        x[i * 4 + 0] = v.x + c.x; x[i * 4 + 1] = v.y + c.y;
        x[i * 4 + 2] = v.z + c.z; x[i * 4 + 3] = v.w + c.w;
        mx = fmaxf(mx, fmaxf(fmaxf(x[i * 4], x[i * 4 + 1]), fmaxf(x[i * 4 + 2], x[i * 4 + 3])));
    }
#pragma unroll
    for (int o = 16; o; o >>= 1) mx = fmaxf(mx, __shfl_xor_sync(0xFFFFFFFFu, mx, o));
    if (lane == 0) red[w] = mx;
    __syncthreads();
    mx = red[0];
#pragma unroll
    for (int i = 1; i < 8; ++i) mx = fmaxf(mx, red[i]);

    float sum = 0.f;
#pragma unroll
    for (int j = 0; j < 32; ++j) { x[j] = __expf(x[j] - mx); sum += x[j]; }
#pragma unroll
    for (int o = 16; o; o >>= 1) sum += __shfl_xor_sync(0xFFFFFFFFu, sum, o);
    __syncthreads();
    if (lane == 0) red[w] = sum;
    __syncthreads();
    sum = 0.f;
#pragma unroll
    for (int i = 0; i < 8; ++i) sum += red[i];
    const float inv = 1.f / sum;

    __half* o = Af + row * ldaf;
#pragma unroll
    for (int i = 0; i < 8; ++i) {
        const size_t base = (size_t)(i * 256 + t) << 2;
        *(__half2*)(o + base)     = __halves2half2(__float2half_rn(x[i * 4] * inv),
                                                   __float2half_rn(x[i * 4 + 1] * inv));
        *(__half2*)(o + base + 2) = __halves2half2(__float2half_rn(x[i * 4 + 2] * inv),
                                                   __float2half_rn(x[i * 4 + 3] * inv));
    }
}

// fp32 -> (bf16 hi, bf16 lo) split, row-major; 4 elems/thread
__global__ __launch_bounds__(256)
void split_rm(const float* __restrict__ X,
              __nv_bfloat16* __restrict__ hi, __nv_bfloat16* __restrict__ lo)
{
    const size_t i = ((size_t)blockIdx.x * 256 + threadIdx.x) << 2;
    float4 v = *(const float4*)(X + i);
    __nv_bfloat16 h0 = __float2bfloat16(v.x), h1 = __float2bfloat16(v.y);
    __nv_bfloat16 h2 = __float2bfloat16(v.z), h3 = __float2bfloat16(v.w);
    *(__nv_bfloat162*)(hi + i)     = __halves2bfloat162(h0, h1);
    *(__nv_bfloat162*)(hi + i + 2) = __halves2bfloat162(h2, h3);
    *(__nv_bfloat162*)(lo + i)     = __halves2bfloat162(
        __float2bfloat16(v.x - __bfloat162float(h0)), __float2bfloat16(v.y - __bfloat162float(h1)));
    *(__nv_bfloat162*)(lo + i + 2) = __halves2bfloat162(
        __float2bfloat16(v.z - __bfloat162float(h2)), __float2bfloat16(v.w - __bfloat162float(h3)));
}

// G_l = scale * W2_l^T W2_l -> bf16 split. grid (RD, NL), RD threads.
__global__ void gmat(const float* __restrict__ W2,
                     __nv_bfloat16* __restrict__ Ghi, __nv_bfloat16* __restrict__ Glo)
{
    const int i = blockIdx.x, l = blockIdx.y, j = threadIdx.x;
    const float* W = W2 + (size_t)l * FD * RD;
    float a = 0.f;
    for (int d = 0; d < FD; ++d) a += W[(size_t)d * RD + i] * W[(size_t)d * RD + j];
    a *= SCALE;
    __nv_bfloat16 h = __float2bfloat16(a);
    const size_t o = (size_t)l * RD * RD + (size_t)i * RD + j;
    Ghi[o] = h;
    Glo[o] = __float2bfloat16(a - __bfloat162float(h));
}

// v_l = scale * W2_l^T b2_l. grid NL, RD threads.
__global__ void vvec(const float* __restrict__ W2, const float* __restrict__ b2,
                     float* __restrict__ v)
{
    const int l = blockIdx.x, r = threadIdx.x;
    const float* W = W2 + (size_t)l * FD * RD;
    const float* b = b2 + (size_t)l * FD;
    float a = 0.f;
    for (int d = 0; d < FD; ++d) a += W[(size_t)d * RD + r] * b[d];
    v[l * RD + r] = a * SCALE;
}

// cv[m] = Hh_f16[m] . v  (v already scaled). grid NH/256.
__global__ __launch_bounds__(256)
void cvec_k(const __half* __restrict__ Hh, const float* __restrict__ v,
            float* __restrict__ cv)
{
    const int m = blockIdx.x * 256 + threadIdx.x;
    const __half* h = Hh + (size_t)m * RD;
    float a = 0.f;
#pragma unroll
    for (int r = 0; r < RD; r += 2) {
        __half2 p = *(const __half2*)(h + r);
        a += __low2float(p) * v[r] + __high2float(p) * v[r + 1];
    }
    cv[m] = a;
}

// bf16 split -> fp16 (sum hi+lo). 4 elems/thread.
__global__ __launch_bounds__(256)
void h2f(const __nv_bfloat16* __restrict__ hi, const __nv_bfloat16* __restrict__ lo,
         __half* __restrict__ o)
{
    const size_t i = ((size_t)blockIdx.x * 256 + threadIdx.x) << 2;
#pragma unroll
    for (int j = 0; j < 4; j += 2) {
        __nv_bfloat162 a = *(const __nv_bfloat162*)(hi + i + j);
        __nv_bfloat162 b = *(const __nv_bfloat162*)(lo + i + j);
        *(__half2*)(o + i + j) = __halves2half2(
            __float2half_rn(__low2float(a) + __low2float(b)),
            __float2half_rn(__high2float(a) + __high2float(b)));
    }
}

// ======================================================================
extern "C" void kernel_launch(void* const* d_in, const int* in_sizes, int n_in,
                              void* d_out, int out_size)
{
    const float* cur  = (const float*)d_in[0];
    const float* hist = (const float*)d_in[1];
    const float* W1   = (const float*)d_in[2];
    const float* b1   = (const float*)d_in[3];
    const float* W2   = (const float*)d_in[4];
    const float* b2   = (const float*)d_in[5];
    const float* Wf   = (const float*)d_in[6];
    const float* bf   = (const float*)d_in[7];
    float* out = (float*)d_out;

    __nv_bfloat16 *Xhi, *Xlo, *W1hi, *W1lo, *Wfhi, *Wflo, *Ghi, *Glo, *Hhi, *Hlo;
    __half *Hhf, *Hcf, *Af, *VfT;
    float *S, *v, *cv;
    cudaGetSymbolAddress((void**)&Xhi, g_Xhi);   cudaGetSymbolAddress((void**)&Xlo, g_Xlo);
    cudaGetSymbolAddress((void**)&W1hi, g_W1hi); cudaGetSymbolAddress((void**)&W1lo, g_W1lo);
    cudaGetSymbolAddress((void**)&Wfhi, g_Wfhi); cudaGetSymbolAddress((void**)&Wflo, g_Wflo);
    cudaGetSymbolAddress((void**)&Ghi, g_Ghi);   cudaGetSymbolAddress((void**)&Glo, g_Glo);
    cudaGetSymbolAddress((void**)&Hhi, g_Hhi);   cudaGetSymbolAddress((void**)&Hlo, g_Hlo);
    cudaGetSymbolAddress((void**)&Hhf, g_Hhf);   cudaGetSymbolAddress((void**)&Hcf, g_Hcf);
    cudaGetSymbolAddress((void**)&Af, g_Af);     cudaGetSymbolAddress((void**)&VfT, g_VfT);
    cudaGetSymbolAddress((void**)&S, g_S);
    cudaGetSymbolAddress((void**)&v, g_v);       cudaGetSymbolAddress((void**)&cv, g_cv);

    cudaFuncSetAttribute(mm128b<true,  1>, cudaFuncAttributeMaxDynamicSharedMemorySize, GSMEM_B);
    cudaFuncSetAttribute(mm128b<false, 2>, cudaFuncAttributeMaxDynamicSharedMemorySize, GSMEM_B);
    cudaFuncSetAttribute(mmh<128>, cudaFuncAttributeMaxDynamicSharedMemorySize,
                         3 * (128 * 128 + TILE_B));
    cudaFuncSetAttribute(mmh<64>,  cudaFuncAttributeMaxDynamicSharedMemorySize,
                         3 * (64 * 128 + TILE_B));

    // ---- preprocessing ----
    split_rm<<<(NC * FD) / 1024, 256>>>(cur,  Xhi,                   Xlo);
    split_rm<<<(NH * FD) / 1024, 256>>>(hist, Xhi + (size_t)NC * FD, Xlo + (size_t)NC * FD);
    split_rm<<<(NL * RD * FD) / 1024, 256>>>(W1, W1hi, W1lo);
    split_rm<<<(FD * NL * FD) / 1024, 256>>>(Wf, Wfhi, Wflo);
    gmat<<<dim3(RD, NL), RD>>>(W2, Ghi, Glo);
    vvec<<<NL, RD>>>(W2, b2, v);

    // VfT_l = Wf_l @ hist^T -> fp16 [FD][NL*NH] blocks   (bf16-3)
    for (int l = 0; l < NL; ++l)
        mm128b<false, 2><<<dim3(NH / 128, FD / 128), 256, GSMEM_B>>>(
            Wfhi + (size_t)l * FD, Wflo + (size_t)l * FD,
            Xhi + (size_t)NC * FD, Xlo + (size_t)NC * FD,
            NL * FD, FD, nullptr,
            nullptr, nullptr, VfT + (size_t)l * NH, LDA_CAT, FD);

    for (int l = 0; l < NL; ++l) {
        const size_t w1o = (size_t)l * RD * FD;

        // H = relu(X @ W1^T + b1)  [NT,RD]  bf16-3 -> split
        mm128b<true, 1><<<dim3(RD / 128, NT / 128), 256, GSMEM_B>>>(
            Xhi, Xlo, W1hi + w1o, W1lo + w1o, FD, FD, b1 + (size_t)l * RD,
            Hhi, Hlo, nullptr, RD, FD);

        // Hh -> fp16
        h2f<<<(NH * RD) / 1024, 256>>>(Hhi + (size_t)NC * RD, Hlo + (size_t)NC * RD, Hhf);

        // Hc' = Hc @ G_l  (G pre-scaled)  bf16-3 -> fp16  [NC,RD]
        mm128b<false, 2><<<dim3(RD / 128, NC / 128), 256, GSMEM_B>>>(
            Hhi, Hlo, Ghi + (size_t)l * RD * RD, Glo + (size_t)l * RD * RD,
            RD, RD, nullptr, nullptr, nullptr, Hcf, RD, RD);

        // cv[m] = Hh[m] . v_l  (pre-scaled)
        cvec_k<<<NH / 256, 256>>>(Hhf, v + l * RD, cv);

        // S = Hc' @ Hh^T   [NC,NH]  fp16, K=128
        mmh<128><<<dim3(NH / 128, NC / 128), 256, 3 * (128 * 128 + TILE_B)>>>(
            Hcf, Hhf, nullptr, S, NH, RD);

        // A_l = softmax(S + cv) -> fp16 at concat col block l
        softmax_h<<<NC, 256>>>(S, cv, Af + (size_t)l * NH, (size_t)LDA_CAT);
    }

    // out = A_cat @ VfT^T + bf   [NC,FD]  fp16, K = NL*NH
    mmh<64><<<dim3(FD / 128, NC / 64), 256, 3 * (64 * 128 + TILE_B)>>>(
        Af, VfT, bf, out, FD, LDA_CAT);
}

// round 9
// speedup vs baseline: 14.9951x; 1.2029x over previous
#include <cuda_runtime.h>
#include <cuda_bf16.h>
#include <cuda_fp16.h>

#define NC 4096
#define NH 8192
#define NT 12288
#define FD 512
#define RD 128
#define NL 3
#define NTILE (NH / 128)          // 64 S-tiles per row

typedef unsigned long long u64;
typedef unsigned int u32;

#define KC 64                     // k elements per chunk
#define TILE_B 16384              // 128 rows x 64 elems x 2B
#define GSMEM_B (2 * 4 * TILE_B)  // bf16-3 kernel: 2 stages x 4 tiles = 128KB
#define GSMEM_SX (2 * 2 * TILE_B) // sexp: 2 stages x (A,B) = 64KB
#define GSMEM_AV (3 * 2 * TILE_B) // av:   3 stages x (A,B) = 96KB

static const float SCALE = 0.044194173824159216f;  // 1/sqrt(512)

// ---------------- helpers ----------------
__device__ __forceinline__ u32 smem_u32(const void* p) {
    u32 a;
    asm("{ .reg .u64 t; cvta.to.shared.u64 t, %1; cvt.u32.u64 %0, t; }" : "=r"(a) : "l"(p));
    return a;
}
__device__ __forceinline__ void ldsm4(u32* r, u32 addr) {
    asm volatile("ldmatrix.sync.aligned.m8n8.x4.shared.b16 {%0,%1,%2,%3}, [%4];"
                 : "=r"(r[0]), "=r"(r[1]), "=r"(r[2]), "=r"(r[3]) : "r"(addr));
}
__device__ __forceinline__ void mma_bf16(float* c, const u32* a, const u32* b) {
    asm volatile("mma.sync.aligned.m16n8k16.row.col.f32.bf16.bf16.f32 "
                 "{%0,%1,%2,%3}, {%4,%5,%6,%7}, {%8,%9}, {%0,%1,%2,%3};"
                 : "+f"(c[0]), "+f"(c[1]), "+f"(c[2]), "+f"(c[3])
                 : "r"(a[0]), "r"(a[1]), "r"(a[2]), "r"(a[3]), "r"(b[0]), "r"(b[1]));
}
__device__ __forceinline__ void mma_f16(float* c, const u32* a, const u32* b) {
    asm volatile("mma.sync.aligned.m16n8k16.row.col.f32.f16.f16.f32 "
                 "{%0,%1,%2,%3}, {%4,%5,%6,%7}, {%8,%9}, {%0,%1,%2,%3};"
                 : "+f"(c[0]), "+f"(c[1]), "+f"(c[2]), "+f"(c[3])
                 : "r"(a[0]), "r"(a[1]), "r"(a[2]), "r"(a[3]), "r"(b[0]), "r"(b[1]));
}
__device__ __forceinline__ u32 swz(u32 base, u32 row, u32 k) {
    return base + row * 128 + ((((k >> 3) ^ (row & 7)) & 7) << 4);
}

// ---------------- scratch ----------------
__device__ __align__(128) __nv_bfloat16 g_Xhi[(size_t)NT * FD],  g_Xlo[(size_t)NT * FD];
__device__ __align__(128) __nv_bfloat16 g_W1hi[(size_t)NL * RD * FD], g_W1lo[(size_t)NL * RD * FD];
__device__ __align__(128) __nv_bfloat16 g_Wfhi[(size_t)FD * NL * FD], g_Wflo[(size_t)FD * NL * FD];
__device__ __align__(128) __nv_bfloat16 g_Ghi[(size_t)NL * RD * RD],  g_Glo[(size_t)NL * RD * RD];
__device__ __align__(128) __nv_bfloat16 g_Hhi[(size_t)NL * NT * RD],  g_Hlo[(size_t)NL * NT * RD];
__device__ __align__(128) __half        g_Hhf[(size_t)NL * NH * RD];  // historical H, fp16
__device__ __align__(128) __half        g_Hcf[(size_t)NL * NC * RD];  // Hc*G*scale, fp16
__device__ __align__(128) __half        g_P  [(size_t)NL * NC * NH];  // exp(s - m_tile) per tile
__device__ __align__(128) float         g_M  [(size_t)NL * NTILE * NC];  // per-tile row max
__device__ __align__(128) float         g_Zp [(size_t)NL * NTILE * NC];  // per-tile row sums
__device__ __align__(128) float         g_F  [(size_t)NL * NTILE * NC];  // exp(M - m_row)
__device__ __align__(128) float         g_Z  [(size_t)NL * NC];       // global row sums
__device__ __align__(128) __half        g_VfT[(size_t)NL * FD * NH];  // Wf_l @ hist^T
__device__ __align__(128) float         g_O  [(size_t)NL * NC * FD];  // per-level outputs
__device__ __align__(128) float         g_v  [NL * RD];
__device__ __align__(128) float         g_cv [NL * NH];

// ======================================================================
// Split-bf16 HMMA GEMM (3 products), z-batched: C = act(A@B^T + bias)
// OM 1: split out (rows<NC) + fp16 out (rows>=NC)   OM 2: fp16 out
// ======================================================================
template<bool RELU, int OM>
__global__ __launch_bounds__(256, 1)
void mm128b(const __nv_bfloat16* __restrict__ Ahi, const __nv_bfloat16* __restrict__ Alo,
            size_t zsA, int lda,
            const __nv_bfloat16* __restrict__ Bhi, const __nv_bfloat16* __restrict__ Blo,
            size_t zsB, int ldb,
            const float* __restrict__ bias, size_t zsBias,
            __nv_bfloat16* __restrict__ Chi, __nv_bfloat16* __restrict__ Clo,
            size_t zsC, int ldcs,
            __half* __restrict__ Ch, size_t zsCh, int ldch,
            int K)
{
    extern __shared__ __align__(1024) char smem[];
    const int tid  = threadIdx.x;
    const int wid  = tid >> 5;
    const int lane = tid & 31;
    const int z  = blockIdx.z;
    const int m0 = blockIdx.y * 128;
    const int n0 = blockIdx.x * 128;
    const int wm = (wid & 1) * 64;
    const int wn = (wid >> 1) * 32;

    const u32 sbase = smem_u32(smem);
    const __nv_bfloat16* srcs[4] = {
        Ahi + zsA * z + (size_t)m0 * lda, Alo + zsA * z + (size_t)m0 * lda,
        Bhi + zsB * z + (size_t)n0 * ldb, Blo + zsB * z + (size_t)n0 * ldb };
    const int lds[4] = { lda, lda, ldb, ldb };

    float acc[4][4][4];
#pragma unroll
    for (int i = 0; i < 4; ++i)
#pragma unroll
        for (int j = 0; j < 4; ++j)
#pragma unroll
            for (int h = 0; h < 4; ++h) acc[i][j][h] = 0.f;

    const u32 a_row = lane & 15;
    const u32 a_k   = (lane >> 4) << 3;
    const u32 b_row = ((lane >> 4) << 3) + (lane & 7);
    const u32 b_k   = ((lane >> 3) & 1) << 3;

    const int nch = K / KC;

    auto load_chunk = [&](int c, int buf) {
        const int kb = c * KC;
        const u32 sb = sbase + buf * 4 * TILE_B;
#pragma unroll
        for (int i = 0; i < 16; ++i) {
            const int t  = i >> 2;
            const int cc = ((i & 3) << 8) + tid;
            const int row = cc >> 3;
            const int k8  = cc & 7;
            const __nv_bfloat16* g = srcs[t] + (size_t)row * lds[t] + kb + (k8 << 3);
            const u32 d = sb + t * TILE_B + row * 128 + (((u32)k8 ^ ((u32)row & 7)) << 4);
            asm volatile("cp.async.cg.shared.global [%0], [%1], 16;" :: "r"(d), "l"(g));
        }
        asm volatile("cp.async.commit_group;" ::: "memory");
    };

    load_chunk(0, 0);

    for (int c = 0; c < nch; ++c) {
        if (c + 1 < nch) {
            load_chunk(c + 1, (c + 1) & 1);
            asm volatile("cp.async.wait_group 1;" ::: "memory");
        } else {
            asm volatile("cp.async.wait_group 0;" ::: "memory");
        }
        __syncthreads();

        const u32 sA_h = sbase + (c & 1) * 4 * TILE_B;
        const u32 sA_l = sA_h + TILE_B;
        const u32 sB_h = sA_h + 2 * TILE_B;
        const u32 sB_l = sA_h + 3 * TILE_B;

#pragma unroll
        for (int ks = 0; ks < 4; ++ks) {
            const u32 kb = ks << 4;
            u32 ah[4][4], al[4][4], bh[2][4], bl[2][4];
#pragma unroll
            for (int mt = 0; mt < 4; ++mt) {
                ldsm4(ah[mt], swz(sA_h, wm + mt * 16 + a_row, kb + a_k));
                ldsm4(al[mt], swz(sA_l, wm + mt * 16 + a_row, kb + a_k));
            }
#pragma unroll
            for (int np = 0; np < 2; ++np) {
                ldsm4(bh[np], swz(sB_h, wn + np * 16 + b_row, kb + b_k));
                ldsm4(bl[np], swz(sB_l, wn + np * 16 + b_row, kb + b_k));
            }
#pragma unroll
            for (int mt = 0; mt < 4; ++mt)
#pragma unroll
                for (int nt = 0; nt < 4; ++nt) {
                    const u32* bhp = &bh[nt >> 1][(nt & 1) * 2];
                    const u32* blp = &bl[nt >> 1][(nt & 1) * 2];
                    mma_bf16(acc[mt][nt], ah[mt], bhp);
                    mma_bf16(acc[mt][nt], ah[mt], blp);
                    mma_bf16(acc[mt][nt], al[mt], bhp);
                }
        }
        __syncthreads();
    }

    const int g  = lane >> 2;
    const int tg = lane & 3;
#pragma unroll
    for (int mt = 0; mt < 4; ++mt)
#pragma unroll
        for (int nt = 0; nt < 4; ++nt) {
            const int cc = n0 + wn + nt * 8 + tg * 2;
#pragma unroll
            for (int h = 0; h < 2; ++h) {
                const int r = m0 + wm + mt * 16 + g + h * 8;
                float v0 = acc[mt][nt][h * 2 + 0];
                float v1 = acc[mt][nt][h * 2 + 1];
                if (bias) { v0 += bias[zsBias * z + cc]; v1 += bias[zsBias * z + cc + 1]; }
                if (RELU) { v0 = fmaxf(v0, 0.f); v1 = fmaxf(v1, 0.f); }
                if (OM == 1) {
                    if (r < NC) {
                        __nv_bfloat16 h0 = __float2bfloat16(v0);
                        __nv_bfloat16 h1 = __float2bfloat16(v1);
                        *(__nv_bfloat162*)(Chi + zsC * z + (size_t)r * ldcs + cc) =
                            __halves2bfloat162(h0, h1);
                        *(__nv_bfloat162*)(Clo + zsC * z + (size_t)r * ldcs + cc) =
                            __halves2bfloat162(
                                __float2bfloat16(v0 - __bfloat162float(h0)),
                                __float2bfloat16(v1 - __bfloat162float(h1)));
                    } else {
                        *(__half2*)(Ch + zsCh * z + (size_t)(r - NC) * ldch + cc) =
                            __halves2half2(__float2half_rn(v0), __float2half_rn(v1));
                    }
                }
                if (OM == 2)
                    *(__half2*)(Ch + zsCh * z + (size_t)r * ldch + cc) =
                        __halves2half2(__float2half_rn(v0), __float2half_rn(v1));
            }
        }
}

// ======================================================================
// S+exp with per-tile row max (flash-style, overflow-proof):
// P_tile = exp(s - m_tile) fp16; M, Zp written per (z, tile, row) (no atomics).
// CTA 128x128, K=128, 2-stage, 256 threads, 2 CTAs/SM.
// ======================================================================
__global__ __launch_bounds__(256, 2)
void sexp_k(const __half* __restrict__ Hcf, const __half* __restrict__ Hhf,
            const float* __restrict__ cv,
            __half* __restrict__ P, float* __restrict__ M, float* __restrict__ Zp)
{
    extern __shared__ __align__(1024) char smem[];
    __shared__ float wred[4][128];   // per-warp-col row max / row sum
    __shared__ float mrow[128];
    const int tid  = threadIdx.x;
    const int wid  = tid >> 5;
    const int lane = tid & 31;
    const int z  = blockIdx.z;
    const int m0 = blockIdx.y * 128;
    const int n0 = blockIdx.x * 128;
    const int wm = (wid & 1) * 64;
    const int wn = (wid >> 1) * 32;
    const int wcol = wid >> 1;

    const u32 sbase = smem_u32(smem);
    const __half* Asrc = Hcf + (size_t)z * NC * RD + (size_t)m0 * RD;
    const __half* Bsrc = Hhf + (size_t)z * NH * RD + (size_t)n0 * RD;

    float acc[4][4][4];
#pragma unroll
    for (int i = 0; i < 4; ++i)
#pragma unroll
        for (int j = 0; j < 4; ++j)
#pragma unroll
            for (int h = 0; h < 4; ++h) acc[i][j][h] = 0.f;

    const u32 a_row = lane & 15;
    const u32 a_k   = (lane >> 4) << 3;
    const u32 b_row = ((lane >> 4) << 3) + (lane & 7);
    const u32 b_k   = ((lane >> 3) & 1) << 3;

    auto load_chunk = [&](int c, int buf) {
        const int kb = c * KC;
        const u32 sb = sbase + buf * 2 * TILE_B;
#pragma unroll
        for (int i = 0; i < 8; ++i) {
            const int t  = i >> 2;
            const int cc = ((i & 3) << 8) + tid;
            const int row = cc >> 3;
            const int k8  = cc & 7;
            const __half* g = (t ? Bsrc : Asrc) + (size_t)row * RD + kb + (k8 << 3);
            const u32 d = sb + t * TILE_B + row * 128 + (((u32)k8 ^ ((u32)row & 7)) << 4);
            asm volatile("cp.async.cg.shared.global [%0], [%1], 16;" :: "r"(d), "l"(g));
        }
        asm volatile("cp.async.commit_group;" ::: "memory");
    };

    load_chunk(0, 0);

    for (int c = 0; c < 2; ++c) {
        if (c == 0) {
            load_chunk(1, 1);
            asm volatile("cp.async.wait_group 1;" ::: "memory");
        } else {
            asm volatile("cp.async.wait_group 0;" ::: "memory");
        }
        __syncthreads();

        const u32 sA = sbase + (c & 1) * 2 * TILE_B;
        const u32 sB = sA + TILE_B;
#pragma unroll
        for (int ks = 0; ks < 4; ++ks) {
            const u32 kb = ks << 4;
            u32 ah[4][4], bh[2][4];
#pragma unroll
            for (int mt = 0; mt < 4; ++mt)
                ldsm4(ah[mt], swz(sA, wm + mt * 16 + a_row, kb + a_k));
#pragma unroll
            for (int np = 0; np < 2; ++np)
                ldsm4(bh[np], swz(sB, wn + np * 16 + b_row, kb + b_k));
#pragma unroll
            for (int mt = 0; mt < 4; ++mt)
#pragma unroll
                for (int nt = 0; nt < 4; ++nt)
                    mma_f16(acc[mt][nt], ah[mt], &bh[nt >> 1][(nt & 1) * 2]);
        }
        __syncthreads();
    }

    const int g  = lane >> 2;
    const int tg = lane & 3;
    const float* cvz = cv + (size_t)z * NH;

    // fold column bias into acc
#pragma unroll
    for (int nt = 0; nt < 4; ++nt) {
        const int cc = n0 + wn + nt * 8 + tg * 2;
        float2 cb = *(const float2*)(cvz + cc);
#pragma unroll
        for (int mt = 0; mt < 4; ++mt)
#pragma unroll
            for (int h = 0; h < 2; ++h) {
                acc[mt][nt][h * 2 + 0] += cb.x;
                acc[mt][nt][h * 2 + 1] += cb.y;
            }
    }

    // pass 1: per-row tile max
#pragma unroll
    for (int mt = 0; mt < 4; ++mt)
#pragma unroll
        for (int h = 0; h < 2; ++h) {
            float mx = -1e30f;
#pragma unroll
            for (int nt = 0; nt < 4; ++nt)
                mx = fmaxf(mx, fmaxf(acc[mt][nt][h * 2], acc[mt][nt][h * 2 + 1]));
            mx = fmaxf(mx, __shfl_xor_sync(0xFFFFFFFFu, mx, 1));
            mx = fmaxf(mx, __shfl_xor_sync(0xFFFFFFFFu, mx, 2));
            if (tg == 0) wred[wcol][wm + mt * 16 + g + h * 8] = mx;
        }
    __syncthreads();
    if (tid < 128)
        mrow[tid] = fmaxf(fmaxf(wred[0][tid], wred[1][tid]),
                          fmaxf(wred[2][tid], wred[3][tid]));
    __syncthreads();

    // pass 2: exp, store P fp16, per-row sums
    __half* Pz = P + (size_t)z * NC * NH;
#pragma unroll
    for (int mt = 0; mt < 4; ++mt)
#pragma unroll
        for (int h = 0; h < 2; ++h) {
            const int lr = wm + mt * 16 + g + h * 8;
            const int r = m0 + lr;
            const float m = mrow[lr];
            float rowacc = 0.f;
#pragma unroll
            for (int nt = 0; nt < 4; ++nt) {
                const int cc = n0 + wn + nt * 8 + tg * 2;
                float e0 = __expf(acc[mt][nt][h * 2 + 0] - m);
                float e1 = __expf(acc[mt][nt][h * 2 + 1] - m);
                *(__half2*)(Pz + (size_t)r * NH + cc) =
                    __halves2half2(__float2half_rn(e0), __float2half_rn(e1));
                rowacc += e0 + e1;
            }
            rowacc += __shfl_xor_sync(0xFFFFFFFFu, rowacc, 1);
            rowacc += __shfl_xor_sync(0xFFFFFFFFu, rowacc, 2);
            if (tg == 0) wred[wcol][lr] = rowacc;   // reuse as sum buffer (after max consumed)
        }
    __syncthreads();
    if (tid < 128) {
        const size_t o = ((size_t)z * NTILE + blockIdx.x) * NC + m0 + tid;
        M[o]  = mrow[tid];
        Zp[o] = wred[0][tid] + wred[1][tid] + wred[2][tid] + wred[3][tid];
    }
}

// per-row global max + Z + per-tile factors. grid (NC/256, NL).
__global__ __launch_bounds__(256)
void sfix(const float* __restrict__ M, const float* __restrict__ Zp,
          float* __restrict__ F, float* __restrict__ Z)
{
    const int z = blockIdx.y;
    const int r = blockIdx.x * 256 + threadIdx.x;
    float m = -1e30f;
    for (int t = 0; t < NTILE; ++t)
        m = fmaxf(m, M[((size_t)z * NTILE + t) * NC + r]);
    float zs = 0.f;
    for (int t = 0; t < NTILE; ++t) {
        const size_t o = ((size_t)z * NTILE + t) * NC + r;
        const float f = __expf(M[o] - m);
        F[o] = f;
        zs += Zp[o] * f;
    }
    Z[(size_t)z * NC + r] = zs;
}

// P[z][r][n] *= F[z][n/128][r]. 8 halves/thread.
__global__ __launch_bounds__(256)
void pfix(__half* __restrict__ P, const float* __restrict__ F)
{
    const size_t base = ((size_t)blockIdx.x * 256 + threadIdx.x) * 8;
    const int z = (int)(base / ((size_t)NC * NH));
    const size_t rem = base - (size_t)z * NC * NH;
    const int r = (int)(rem / NH);
    const int n = (int)(rem - (size_t)r * NH);
    const float f = F[((size_t)z * NTILE + (n >> 7)) * NC + r];
    uint4 v = *(uint4*)(P + base);
    __half2* hp = (__half2*)&v;
#pragma unroll
    for (int j = 0; j < 4; ++j) {
        float2 x = __half22float2(hp[j]);
        hp[j] = __halves2half2(__float2half_rn(x.x * f), __float2half_rn(x.y * f));
    }
    *(uint4*)(P + base) = v;
}

// ======================================================================
// AV: O_l = (P_l @ VfT_l^T) / Z_l[row], f32 out. K=NH, 3-stage.
// ======================================================================
__global__ __launch_bounds__(256, 2)
void av_k(const __half* __restrict__ P, const __half* __restrict__ VfT,
          const float* __restrict__ Z, float* __restrict__ O)
{
    extern __shared__ __align__(1024) char smem[];
    const int tid  = threadIdx.x;
    const int wid  = tid >> 5;
    const int lane = tid & 31;
    const int z  = blockIdx.z;
    const int m0 = blockIdx.y * 128;
    const int n0 = blockIdx.x * 128;
    const int wm = (wid & 1) * 64;
    const int wn = (wid >> 1) * 32;

    const u32 sbase = smem_u32(smem);
    const __half* Asrc = P   + (size_t)z * NC * NH + (size_t)m0 * NH;
    const __half* Bsrc = VfT + (size_t)z * FD * NH + (size_t)n0 * NH;

    float acc[4][4][4];
#pragma unroll
    for (int i = 0; i < 4; ++i)
#pragma unroll
        for (int j = 0; j < 4; ++j)
#pragma unroll
            for (int h = 0; h < 4; ++h) acc[i][j][h] = 0.f;

    const u32 a_row = lane & 15;
    const u32 a_k   = (lane >> 4) << 3;
    const u32 b_row = ((lane >> 4) << 3) + (lane & 7);
    const u32 b_k   = ((lane >> 3) & 1) << 3;

    const int nch = NH / KC;   // 128

    auto load_chunk = [&](int c) {
        const int kb = c * KC;
        const u32 sb = sbase + (c % 3) * 2 * TILE_B;
#pragma unroll
        for (int i = 0; i < 8; ++i) {
            const int t  = i >> 2;
            const int cc = ((i & 3) << 8) + tid;
            const int row = cc >> 3;
            const int k8  = cc & 7;
            const __half* g = (t ? Bsrc : Asrc) + (size_t)row * NH + kb + (k8 << 3);
            const u32 d = sb + t * TILE_B + row * 128 + (((u32)k8 ^ ((u32)row & 7)) << 4);
            asm volatile("cp.async.cg.shared.global [%0], [%1], 16;" :: "r"(d), "l"(g));
        }
        asm volatile("cp.async.commit_group;" ::: "memory");
    };

    load_chunk(0);
    load_chunk(1);

    for (int c = 0; c < nch; ++c) {
        if (c + 1 < nch) { asm volatile("cp.async.wait_group 1;" ::: "memory"); }
        else             { asm volatile("cp.async.wait_group 0;" ::: "memory"); }
        __syncthreads();
        if (c + 2 < nch) load_chunk(c + 2);

        const u32 sA = sbase + (c % 3) * 2 * TILE_B;
        const u32 sB = sA + TILE_B;
#pragma unroll
        for (int ks = 0; ks < 4; ++ks) {
            const u32 kb = ks << 4;
            u32 ah[4][4], bh[2][4];
#pragma unroll
            for (int mt = 0; mt < 4; ++mt)
                ldsm4(ah[mt], swz(sA, wm + mt * 16 + a_row, kb + a_k));
#pragma unroll
            for (int np = 0; np < 2; ++np)
                ldsm4(bh[np], swz(sB, wn + np * 16 + b_row, kb + b_k));
#pragma unroll
            for (int mt = 0; mt < 4; ++mt)
#pragma unroll
                for (int nt = 0; nt < 4; ++nt)
                    mma_f16(acc[mt][nt], ah[mt], &bh[nt >> 1][(nt & 1) * 2]);
        }
    }

    const int g  = lane >> 2;
    const int tg = lane & 3;
    float* Oz = O + (size_t)z * NC * FD;
#pragma unroll
    for (int mt = 0; mt < 4; ++mt)
#pragma unroll
        for (int h = 0; h < 2; ++h) {
            const int r = m0 + wm + mt * 16 + g + h * 8;
            const float iz = 1.f / Z[(size_t)z * NC + r];
#pragma unroll
            for (int nt = 0; nt < 4; ++nt) {
                const int cc = n0 + wn + nt * 8 + tg * 2;
                *(float2*)(Oz + (size_t)r * FD + cc) =
                    make_float2(acc[mt][nt][h * 2 + 0] * iz, acc[mt][nt][h * 2 + 1] * iz);
            }
        }
}

// ---------------- small kernels ----------------
__global__ __launch_bounds__(256)
void split_rm(const float* __restrict__ X,
              __nv_bfloat16* __restrict__ hi, __nv_bfloat16* __restrict__ lo)
{
    const size_t i = ((size_t)blockIdx.x * 256 + threadIdx.x) << 2;
    float4 v = *(const float4*)(X + i);
    __nv_bfloat16 h0 = __float2bfloat16(v.x), h1 = __float2bfloat16(v.y);
    __nv_bfloat16 h2 = __float2bfloat16(v.z), h3 = __float2bfloat16(v.w);
    *(__nv_bfloat162*)(hi + i)     = __halves2bfloat162(h0, h1);
    *(__nv_bfloat162*)(hi + i + 2) = __halves2bfloat162(h2, h3);
    *(__nv_bfloat162*)(lo + i)     = __halves2bfloat162(
        __float2bfloat16(v.x - __bfloat162float(h0)), __float2bfloat16(v.y - __bfloat162float(h1)));
    *(__nv_bfloat162*)(lo + i + 2) = __halves2bfloat162(
        __float2bfloat16(v.z - __bfloat162float(h2)), __float2bfloat16(v.w - __bfloat162float(h3)));
}

__global__ void gmat(const float* __restrict__ W2,
                     __nv_bfloat16* __restrict__ Ghi, __nv_bfloat16* __restrict__ Glo)
{
    const int i = blockIdx.x, l = blockIdx.y, j = threadIdx.x;
    const float* W = W2 + (size_t)l * FD * RD;
    float a = 0.f;
    for (int d = 0; d < FD; ++d) a += W[(size_t)d * RD + i] * W[(size_t)d * RD + j];
    a *= SCALE;
    __nv_bfloat16 h = __float2bfloat16(a);
    const size_t o = (size_t)l * RD * RD + (size_t)i * RD + j;
    Ghi[o] = h;
    Glo[o] = __float2bfloat16(a - __bfloat162float(h));
}

__global__ void vvec(const float* __restrict__ W2, const float* __restrict__ b2,
                     float* __restrict__ v)
{
    const int l = blockIdx.x, r = threadIdx.x;
    const float* W = W2 + (size_t)l * FD * RD;
    const float* b = b2 + (size_t)l * FD;
    float a = 0.f;
    for (int d = 0; d < FD; ++d) a += W[(size_t)d * RD + r] * b[d];
    v[l * RD + r] = a * SCALE;
}

__global__ __launch_bounds__(256)
void cvec_k(const __half* __restrict__ Hhf, const float* __restrict__ v,
            float* __restrict__ cv)
{
    const int z = blockIdx.y;
    const int m = blockIdx.x * 256 + threadIdx.x;
    const __half* h = Hhf + (size_t)z * NH * RD + (size_t)m * RD;
    const float* vz = v + z * RD;
    float a = 0.f;
#pragma unroll
    for (int r = 0; r < RD; r += 2) {
        __half2 p = *(const __half2*)(h + r);
        a += __low2float(p) * vz[r] + __high2float(p) * vz[r + 1];
    }
    cv[(size_t)z * NH + m] = a;
}

__global__ __launch_bounds__(256)
void combine(const float* __restrict__ O, const float* __restrict__ bf,
             float* __restrict__ out)
{
    const size_t i = ((size_t)blockIdx.x * 256 + threadIdx.x) << 2;
    const int col = (int)(i & (FD - 1));
    float4 b  = *(const float4*)(bf + col);
    float4 a0 = *(const float4*)(O + i);
    float4 a1 = *(const float4*)(O + (size_t)NC * FD + i);
    float4 a2 = *(const float4*)(O + (size_t)2 * NC * FD + i);
    *(float4*)(out + i) = make_float4(b.x + a0.x + a1.x + a2.x,
                                      b.y + a0.y + a1.y + a2.y,
                                      b.z + a0.z + a1.z + a2.z,
                                      b.w + a0.w + a1.w + a2.w);
}

// ======================================================================
extern "C" void kernel_launch(void* const* d_in, const int* in_sizes, int n_in,
                              void* d_out, int out_size)
{
    const float* cur  = (const float*)d_in[0];
    const float* hist = (const float*)d_in[1];
    const float* W1   = (const float*)d_in[2];
    const float* b1   = (const float*)d_in[3];
    const float* W2   = (const float*)d_in[4];
    const float* b2   = (const float*)d_in[5];
    const float* Wf   = (const float*)d_in[6];
    const float* bf   = (const float*)d_in[7];
    float* out = (float*)d_out;

    __nv_bfloat16 *Xhi, *Xlo, *W1hi, *W1lo, *Wfhi, *Wflo, *Ghi, *Glo, *Hhi, *Hlo;
    __half *Hhf, *Hcf, *P, *VfT;
    float *Z, *O, *v, *cv, *M, *Zp, *F;
    cudaGetSymbolAddress((void**)&Xhi, g_Xhi);   cudaGetSymbolAddress((void**)&Xlo, g_Xlo);
    cudaGetSymbolAddress((void**)&W1hi, g_W1hi); cudaGetSymbolAddress((void**)&W1lo, g_W1lo);
    cudaGetSymbolAddress((void**)&Wfhi, g_Wfhi); cudaGetSymbolAddress((void**)&Wflo, g_Wflo);
    cudaGetSymbolAddress((void**)&Ghi, g_Ghi);   cudaGetSymbolAddress((void**)&Glo, g_Glo);
    cudaGetSymbolAddress((void**)&Hhi, g_Hhi);   cudaGetSymbolAddress((void**)&Hlo, g_Hlo);
    cudaGetSymbolAddress((void**)&Hhf, g_Hhf);   cudaGetSymbolAddress((void**)&Hcf, g_Hcf);
    cudaGetSymbolAddress((void**)&P, g_P);       cudaGetSymbolAddress((void**)&VfT, g_VfT);
    cudaGetSymbolAddress((void**)&Z, g_Z);       cudaGetSymbolAddress((void**)&O, g_O);
    cudaGetSymbolAddress((void**)&v, g_v);       cudaGetSymbolAddress((void**)&cv, g_cv);
    cudaGetSymbolAddress((void**)&M, g_M);       cudaGetSymbolAddress((void**)&Zp, g_Zp);
    cudaGetSymbolAddress((void**)&F, g_F);

    cudaFuncSetAttribute(mm128b<true,  1>, cudaFuncAttributeMaxDynamicSharedMemorySize, GSMEM_B);
    cudaFuncSetAttribute(mm128b<false, 2>, cudaFuncAttributeMaxDynamicSharedMemorySize, GSMEM_B);
    cudaFuncSetAttribute(sexp_k, cudaFuncAttributeMaxDynamicSharedMemorySize, GSMEM_SX);
    cudaFuncSetAttribute(av_k,   cudaFuncAttributeMaxDynamicSharedMemorySize, GSMEM_AV);

    // ---- preprocessing ----
    split_rm<<<(NC * FD) / 1024, 256>>>(cur,  Xhi,                   Xlo);
    split_rm<<<(NH * FD) / 1024, 256>>>(hist, Xhi + (size_t)NC * FD, Xlo + (size_t)NC * FD);
    split_rm<<<(NL * RD * FD) / 1024, 256>>>(W1, W1hi, W1lo);
    split_rm<<<(FD * NL * FD) / 1024, 256>>>(Wf, Wfhi, Wflo);
    gmat<<<dim3(RD, NL), RD>>>(W2, Ghi, Glo);
    vvec<<<NL, RD>>>(W2, b2, v);

    // VfT_l = Wf_l @ hist^T  [FD, NH] fp16 (bf16-3)
    mm128b<false, 2><<<dim3(NH / 128, FD / 128, NL), 256, GSMEM_B>>>(
        Wfhi, Wflo, (size_t)FD, NL * FD,
        Xhi + (size_t)NC * FD, Xlo + (size_t)NC * FD, 0, FD,
        nullptr, 0,
        nullptr, nullptr, 0, 0,
        VfT, (size_t)FD * NH, NH, FD);

    // H_l = relu(X @ W1_l^T + b1_l): split (rows<NC) + fp16 (rows>=NC)
    mm128b<true, 1><<<dim3(RD / 128, NT / 128, NL), 256, GSMEM_B>>>(
        Xhi, Xlo, 0, FD,
        W1hi, W1lo, (size_t)RD * FD, FD,
        b1, (size_t)RD,
        Hhi, Hlo, (size_t)NT * RD, RD,
        Hhf, (size_t)NH * RD, RD, FD);

    // cv[z] = Hhf[z] . v[z]
    cvec_k<<<dim3(NH / 256, NL), 256>>>(Hhf, v, cv);

    // Hc'_l = Hc_l @ G_l (pre-scaled)  [NC, RD] fp16
    mm128b<false, 2><<<dim3(RD / 128, NC / 128, NL), 256, GSMEM_B>>>(
        Hhi, Hlo, (size_t)NT * RD, RD,
        Ghi, Glo, (size_t)RD * RD, RD,
        nullptr, 0,
        nullptr, nullptr, 0, 0,
        Hcf, (size_t)NC * RD, RD, RD);

    // P = exp(s - m_tile) per tile; M, Zp partials
    sexp_k<<<dim3(NH / 128, NC / 128, NL), 256, GSMEM_SX>>>(Hcf, Hhf, cv, P, M, Zp);

    // global row max / Z / per-tile factors, then rescale P
    sfix<<<dim3(NC / 256, NL), 256>>>(M, Zp, F, Z);
    pfix<<<(int)(((size_t)NL * NC * NH) / 2048), 256>>>(P, F);

    // O_l = (P_l @ VfT_l^T) / Z_l
    av_k<<<dim3(FD / 128, NC / 128, NL), 256, GSMEM_AV>>>(P, VfT, Z, O);

    // out = bf + sum_l O_l
    combine<<<(NC * FD) / 1024, 256>>>(O, bf, out);
}

// round 10
// speedup vs baseline: 16.0684x; 1.0716x over previous
#include <cuda_runtime.h>
#include <cuda_bf16.h>
#include <cuda_fp16.h>

#define NC 4096
#define NH 8192
#define NT 12288
#define FD 512
#define RD 128
#define NL 3
#define NTILE (NH / 128)          // 64 S-tiles per row

typedef unsigned long long u64;
typedef unsigned int u32;

#define KC 64                     // k elements per chunk
#define TILE_B 16384              // 128 rows x 64 elems x 2B
#define GSMEM_B (2 * 4 * TILE_B)  // bf16-3 kernel: 2 stages x 4 tiles = 128KB
#define GSMEM_SX (2 * 2 * TILE_B) // sexp: 2 stages x (A,B) = 64KB
#define GSMEM_V  (3 * 2 * TILE_B) // vft: 3 stages x (A,B) = 96KB

// AV kernel tiling
#define AV_BM 32
#define AV_BN 256
#define AV_TA (AV_BM * 128)            // 4KB
#define AV_TB (AV_BN * 128)            // 32KB
#define AV_STAGE (AV_TA + AV_TB)       // 36KB
#define GSMEM_AV (2 * AV_STAGE)        // 72KB

static const float SCALE = 0.044194173824159216f;  // 1/sqrt(512)

// ---------------- helpers ----------------
__device__ __forceinline__ u32 smem_u32(const void* p) {
    u32 a;
    asm("{ .reg .u64 t; cvta.to.shared.u64 t, %1; cvt.u32.u64 %0, t; }" : "=r"(a) : "l"(p));
    return a;
}
__device__ __forceinline__ void ldsm4(u32* r, u32 addr) {
    asm volatile("ldmatrix.sync.aligned.m8n8.x4.shared.b16 {%0,%1,%2,%3}, [%4];"
                 : "=r"(r[0]), "=r"(r[1]), "=r"(r[2]), "=r"(r[3]) : "r"(addr));
}
__device__ __forceinline__ void mma_bf16(float* c, const u32* a, const u32* b) {
    asm volatile("mma.sync.aligned.m16n8k16.row.col.f32.bf16.bf16.f32 "
                 "{%0,%1,%2,%3}, {%4,%5,%6,%7}, {%8,%9}, {%0,%1,%2,%3};"
                 : "+f"(c[0]), "+f"(c[1]), "+f"(c[2]), "+f"(c[3])
                 : "r"(a[0]), "r"(a[1]), "r"(a[2]), "r"(a[3]), "r"(b[0]), "r"(b[1]));
}
__device__ __forceinline__ void mma_f16(float* c, const u32* a, const u32* b) {
    asm volatile("mma.sync.aligned.m16n8k16.row.col.f32.f16.f16.f32 "
                 "{%0,%1,%2,%3}, {%4,%5,%6,%7}, {%8,%9}, {%0,%1,%2,%3};"
                 : "+f"(c[0]), "+f"(c[1]), "+f"(c[2]), "+f"(c[3])
                 : "r"(a[0]), "r"(a[1]), "r"(a[2]), "r"(a[3]), "r"(b[0]), "r"(b[1]));
}
__device__ __forceinline__ u32 swz(u32 base, u32 row, u32 k) {
    return base + row * 128 + ((((k >> 3) ^ (row & 7)) & 7) << 4);
}

// ---------------- scratch ----------------
__device__ __align__(128) __nv_bfloat16 g_Xhi[(size_t)NT * FD],  g_Xlo[(size_t)NT * FD];
__device__ __align__(128) __nv_bfloat16 g_W1hi[(size_t)NL * RD * FD], g_W1lo[(size_t)NL * RD * FD];
__device__ __align__(128) __nv_bfloat16 g_Ghi[(size_t)NL * RD * RD],  g_Glo[(size_t)NL * RD * RD];
__device__ __align__(128) __nv_bfloat16 g_Hhi[(size_t)NL * NT * RD],  g_Hlo[(size_t)NL * NT * RD];
__device__ __align__(128) __half        g_Wf16[(size_t)FD * NL * FD]; // Wf fp16
__device__ __align__(128) __half        g_X16 [(size_t)NH * FD];      // hist fp16
__device__ __align__(128) __half        g_Hhf[(size_t)NL * NH * RD];  // historical H, fp16
__device__ __align__(128) __half        g_Hcf[(size_t)NL * NC * RD];  // Hc*G*scale, fp16
__device__ __align__(128) __half        g_P  [(size_t)NL * NC * NH];  // exp(s - m_tile) per tile
__device__ __align__(128) float         g_M  [(size_t)NL * NTILE * NC];  // per-tile row max
__device__ __align__(128) float         g_Zp [(size_t)NL * NTILE * NC];  // per-tile row sums
__device__ __align__(128) float         g_F  [(size_t)NL * NTILE * NC];  // exp(M - m_row) / Z
__device__ __align__(128) __half        g_VfT[(size_t)NL * FD * NH];  // Wf_l @ hist^T
__device__ __align__(128) float         g_v  [NL * RD];
__device__ __align__(128) float         g_cv [NL * NH];

// ======================================================================
// Split-bf16 HMMA GEMM (3 products), z-batched: C = act(A@B^T + bias)
// OM 1: split out (rows<NC) + fp16 out (rows>=NC)   OM 2: fp16 out
// ======================================================================
template<bool RELU, int OM>
__global__ __launch_bounds__(256, 1)
void mm128b(const __nv_bfloat16* __restrict__ Ahi, const __nv_bfloat16* __restrict__ Alo,
            size_t zsA, int lda,
            const __nv_bfloat16* __restrict__ Bhi, const __nv_bfloat16* __restrict__ Blo,
            size_t zsB, int ldb,
            const float* __restrict__ bias, size_t zsBias,
            __nv_bfloat16* __restrict__ Chi, __nv_bfloat16* __restrict__ Clo,
            size_t zsC, int ldcs,
            __half* __restrict__ Ch, size_t zsCh, int ldch,
            int K)
{
    extern __shared__ __align__(1024) char smem[];
    const int tid  = threadIdx.x;
    const int wid  = tid >> 5;
    const int lane = tid & 31;
    const int z  = blockIdx.z;
    const int m0 = blockIdx.y * 128;
    const int n0 = blockIdx.x * 128;
    const int wm = (wid & 1) * 64;
    const int wn = (wid >> 1) * 32;

    const u32 sbase = smem_u32(smem);
    const __nv_bfloat16* srcs[4] = {
        Ahi + zsA * z + (size_t)m0 * lda, Alo + zsA * z + (size_t)m0 * lda,
        Bhi + zsB * z + (size_t)n0 * ldb, Blo + zsB * z + (size_t)n0 * ldb };
    const int lds[4] = { lda, lda, ldb, ldb };

    float acc[4][4][4];
#pragma unroll
    for (int i = 0; i < 4; ++i)
#pragma unroll
        for (int j = 0; j < 4; ++j)
#pragma unroll
            for (int h = 0; h < 4; ++h) acc[i][j][h] = 0.f;

    const u32 a_row = lane & 15;
    const u32 a_k   = (lane >> 4) << 3;
    const u32 b_row = ((lane >> 4) << 3) + (lane & 7);
    const u32 b_k   = ((lane >> 3) & 1) << 3;

    const int nch = K / KC;

    auto load_chunk = [&](int c, int buf) {
        const int kb = c * KC;
        const u32 sb = sbase + buf * 4 * TILE_B;
#pragma unroll
        for (int i = 0; i < 16; ++i) {
            const int t  = i >> 2;
            const int cc = ((i & 3) << 8) + tid;
            const int row = cc >> 3;
            const int k8  = cc & 7;
            const __nv_bfloat16* g = srcs[t] + (size_t)row * lds[t] + kb + (k8 << 3);
            const u32 d = sb + t * TILE_B + row * 128 + (((u32)k8 ^ ((u32)row & 7)) << 4);
            asm volatile("cp.async.cg.shared.global [%0], [%1], 16;" :: "r"(d), "l"(g));
        }
        asm volatile("cp.async.commit_group;" ::: "memory");
    };

    load_chunk(0, 0);

    for (int c = 0; c < nch; ++c) {
        if (c + 1 < nch) {
            load_chunk(c + 1, (c + 1) & 1);
            asm volatile("cp.async.wait_group 1;" ::: "memory");
        } else {
            asm volatile("cp.async.wait_group 0;" ::: "memory");
        }
        __syncthreads();

        const u32 sA_h = sbase + (c & 1) * 4 * TILE_B;
        const u32 sA_l = sA_h + TILE_B;
        const u32 sB_h = sA_h + 2 * TILE_B;
        const u32 sB_l = sA_h + 3 * TILE_B;

#pragma unroll
        for (int ks = 0; ks < 4; ++ks) {
            const u32 kb = ks << 4;
            u32 ah[4][4], al[4][4], bh[2][4], bl[2][4];
#pragma unroll
            for (int mt = 0; mt < 4; ++mt) {
                ldsm4(ah[mt], swz(sA_h, wm + mt * 16 + a_row, kb + a_k));
                ldsm4(al[mt], swz(sA_l, wm + mt * 16 + a_row, kb + a_k));
            }
#pragma unroll
            for (int np = 0; np < 2; ++np) {
                ldsm4(bh[np], swz(sB_h, wn + np * 16 + b_row, kb + b_k));
                ldsm4(bl[np], swz(sB_l, wn + np * 16 + b_row, kb + b_k));
            }
#pragma unroll
            for (int mt = 0; mt < 4; ++mt)
#pragma unroll
                for (int nt = 0; nt < 4; ++nt) {
                    const u32* bhp = &bh[nt >> 1][(nt & 1) * 2];
                    const u32* blp = &bl[nt >> 1][(nt & 1) * 2];
                    mma_bf16(acc[mt][nt], ah[mt], bhp);
                    mma_bf16(acc[mt][nt], ah[mt], blp);
                    mma_bf16(acc[mt][nt], al[mt], bhp);
                }
        }
        __syncthreads();
    }

    const int g  = lane >> 2;
    const int tg = lane & 3;
#pragma unroll
    for (int mt = 0; mt < 4; ++mt)
#pragma unroll
        for (int nt = 0; nt < 4; ++nt) {
            const int cc = n0 + wn + nt * 8 + tg * 2;
#pragma unroll
            for (int h = 0; h < 2; ++h) {
                const int r = m0 + wm + mt * 16 + g + h * 8;
                float v0 = acc[mt][nt][h * 2 + 0];
                float v1 = acc[mt][nt][h * 2 + 1];
                if (bias) { v0 += bias[zsBias * z + cc]; v1 += bias[zsBias * z + cc + 1]; }
                if (RELU) { v0 = fmaxf(v0, 0.f); v1 = fmaxf(v1, 0.f); }
                if (OM == 1) {
                    if (r < NC) {
                        __nv_bfloat16 h0 = __float2bfloat16(v0);
                        __nv_bfloat16 h1 = __float2bfloat16(v1);
                        *(__nv_bfloat162*)(Chi + zsC * z + (size_t)r * ldcs + cc) =
                            __halves2bfloat162(h0, h1);
                        *(__nv_bfloat162*)(Clo + zsC * z + (size_t)r * ldcs + cc) =
                            __halves2bfloat162(
                                __float2bfloat16(v0 - __bfloat162float(h0)),
                                __float2bfloat16(v1 - __bfloat162float(h1)));
                    } else {
                        *(__half2*)(Ch + zsCh * z + (size_t)(r - NC) * ldch + cc) =
                            __halves2half2(__float2half_rn(v0), __float2half_rn(v1));
                    }
                }
                if (OM == 2)
                    *(__half2*)(Ch + zsCh * z + (size_t)r * ldch + cc) =
                        __halves2half2(__float2half_rn(v0), __float2half_rn(v1));
            }
        }
}

// ======================================================================
// fp16 single-product GEMM for VfT: C[FD,NH] = Wf_l @ hist^T, fp16 out.
// CTA 128x128, 3-stage, 256 threads, 2 CTAs/SM, z-batched.
// ======================================================================
__global__ __launch_bounds__(256, 2)
void vft_k(const __half* __restrict__ A, const __half* __restrict__ B,
           __half* __restrict__ C)
{
    extern __shared__ __align__(1024) char smem[];
    const int tid  = threadIdx.x;
    const int wid  = tid >> 5;
    const int lane = tid & 31;
    const int z  = blockIdx.z;
    const int m0 = blockIdx.y * 128;     // FD rows
    const int n0 = blockIdx.x * 128;     // NH rows
    const int wm = (wid & 1) * 64;
    const int wn = (wid >> 1) * 32;

    const u32 sbase = smem_u32(smem);
    const __half* Asrc = A + (size_t)z * FD + (size_t)m0 * (NL * FD);  // lda = NL*FD
    const __half* Bsrc = B + (size_t)n0 * FD;                          // ldb = FD

    float acc[4][4][4];
#pragma unroll
    for (int i = 0; i < 4; ++i)
#pragma unroll
        for (int j = 0; j < 4; ++j)
#pragma unroll
            for (int h = 0; h < 4; ++h) acc[i][j][h] = 0.f;

    const u32 a_row = lane & 15;
    const u32 a_k   = (lane >> 4) << 3;
    const u32 b_row = ((lane >> 4) << 3) + (lane & 7);
    const u32 b_k   = ((lane >> 3) & 1) << 3;

    const int nch = FD / KC;   // 8

    auto load_chunk = [&](int c) {
        const int kb = c * KC;
        const u32 sb = sbase + (c % 3) * 2 * TILE_B;
#pragma unroll
        for (int i = 0; i < 8; ++i) {
            const int t  = i >> 2;
            const int cc = ((i & 3) << 8) + tid;
            const int row = cc >> 3;
            const int k8  = cc & 7;
            const __half* g = (t ? (Bsrc + (size_t)row * FD) : (Asrc + (size_t)row * (NL * FD)))
                              + kb + (k8 << 3);
            const u32 d = sb + t * TILE_B + row * 128 + (((u32)k8 ^ ((u32)row & 7)) << 4);
            asm volatile("cp.async.cg.shared.global [%0], [%1], 16;" :: "r"(d), "l"(g));
        }
        asm volatile("cp.async.commit_group;" ::: "memory");
    };

    load_chunk(0);
    load_chunk(1);

    for (int c = 0; c < nch; ++c) {
        if (c + 1 < nch) { asm volatile("cp.async.wait_group 1;" ::: "memory"); }
        else             { asm volatile("cp.async.wait_group 0;" ::: "memory"); }
        __syncthreads();
        if (c + 2 < nch) load_chunk(c + 2);

        const u32 sA = sbase + (c % 3) * 2 * TILE_B;
        const u32 sB = sA + TILE_B;
#pragma unroll
        for (int ks = 0; ks < 4; ++ks) {
            const u32 kb = ks << 4;
            u32 ah[4][4], bh[2][4];
#pragma unroll
            for (int mt = 0; mt < 4; ++mt)
                ldsm4(ah[mt], swz(sA, wm + mt * 16 + a_row, kb + a_k));
#pragma unroll
            for (int np = 0; np < 2; ++np)
                ldsm4(bh[np], swz(sB, wn + np * 16 + b_row, kb + b_k));
#pragma unroll
            for (int mt = 0; mt < 4; ++mt)
#pragma unroll
                for (int nt = 0; nt < 4; ++nt)
                    mma_f16(acc[mt][nt], ah[mt], &bh[nt >> 1][(nt & 1) * 2]);
        }
    }

    const int g  = lane >> 2;
    const int tg = lane & 3;
    __half* Cz = C + (size_t)z * FD * NH;
#pragma unroll
    for (int mt = 0; mt < 4; ++mt)
#pragma unroll
        for (int nt = 0; nt < 4; ++nt) {
            const int cc = n0 + wn + nt * 8 + tg * 2;
#pragma unroll
            for (int h = 0; h < 2; ++h) {
                const int r = m0 + wm + mt * 16 + g + h * 8;
                *(__half2*)(Cz + (size_t)r * NH + cc) =
                    __halves2half2(__float2half_rn(acc[mt][nt][h * 2 + 0]),
                                   __float2half_rn(acc[mt][nt][h * 2 + 1]));
            }
        }
}

// ======================================================================
// S+exp with per-tile row max (flash-style, overflow-proof):
// P_tile = exp(s - m_tile) fp16; M, Zp per (z, tile, row), no atomics.
// ======================================================================
__global__ __launch_bounds__(256, 2)
void sexp_k(const __half* __restrict__ Hcf, const __half* __restrict__ Hhf,
            const float* __restrict__ cv,
            __half* __restrict__ P, float* __restrict__ M, float* __restrict__ Zp)
{
    extern __shared__ __align__(1024) char smem[];
    __shared__ float wred[4][128];
    __shared__ float mrow[128];
    const int tid  = threadIdx.x;
    const int wid  = tid >> 5;
    const int lane = tid & 31;
    const int z  = blockIdx.z;
    const int m0 = blockIdx.y * 128;
    const int n0 = blockIdx.x * 128;
    const int wm = (wid & 1) * 64;
    const int wn = (wid >> 1) * 32;
    const int wcol = wid >> 1;

    const u32 sbase = smem_u32(smem);
    const __half* Asrc = Hcf + (size_t)z * NC * RD + (size_t)m0 * RD;
    const __half* Bsrc = Hhf + (size_t)z * NH * RD + (size_t)n0 * RD;

    float acc[4][4][4];
#pragma unroll
    for (int i = 0; i < 4; ++i)
#pragma unroll
        for (int j = 0; j < 4; ++j)
#pragma unroll
            for (int h = 0; h < 4; ++h) acc[i][j][h] = 0.f;

    const u32 a_row = lane & 15;
    const u32 a_k   = (lane >> 4) << 3;
    const u32 b_row = ((lane >> 4) << 3) + (lane & 7);
    const u32 b_k   = ((lane >> 3) & 1) << 3;

    auto load_chunk = [&](int c, int buf) {
        const int kb = c * KC;
        const u32 sb = sbase + buf * 2 * TILE_B;
#pragma unroll
        for (int i = 0; i < 8; ++i) {
            const int t  = i >> 2;
            const int cc = ((i & 3) << 8) + tid;
            const int row = cc >> 3;
            const int k8  = cc & 7;
            const __half* g = (t ? Bsrc : Asrc) + (size_t)row * RD + kb + (k8 << 3);
            const u32 d = sb + t * TILE_B + row * 128 + (((u32)k8 ^ ((u32)row & 7)) << 4);
            asm volatile("cp.async.cg.shared.global [%0], [%1], 16;" :: "r"(d), "l"(g));
        }
        asm volatile("cp.async.commit_group;" ::: "memory");
    };

    load_chunk(0, 0);

    for (int c = 0; c < 2; ++c) {
        if (c == 0) {
            load_chunk(1, 1);
            asm volatile("cp.async.wait_group 1;" ::: "memory");
        } else {
            asm volatile("cp.async.wait_group 0;" ::: "memory");
        }
        __syncthreads();

        const u32 sA = sbase + (c & 1) * 2 * TILE_B;
        const u32 sB = sA + TILE_B;
#pragma unroll
        for (int ks = 0; ks < 4; ++ks) {
            const u32 kb = ks << 4;
            u32 ah[4][4], bh[2][4];
#pragma unroll
            for (int mt = 0; mt < 4; ++mt)
                ldsm4(ah[mt], swz(sA, wm + mt * 16 + a_row, kb + a_k));
#pragma unroll
            for (int np = 0; np < 2; ++np)
                ldsm4(bh[np], swz(sB, wn + np * 16 + b_row, kb + b_k));
#pragma unroll
            for (int mt = 0; mt < 4; ++mt)
#pragma unroll
                for (int nt = 0; nt < 4; ++nt)
                    mma_f16(acc[mt][nt], ah[mt], &bh[nt >> 1][(nt & 1) * 2]);
        }
        __syncthreads();
    }

    const int g  = lane >> 2;
    const int tg = lane & 3;
    const float* cvz = cv + (size_t)z * NH;

#pragma unroll
    for (int nt = 0; nt < 4; ++nt) {
        const int cc = n0 + wn + nt * 8 + tg * 2;
        float2 cb = *(const float2*)(cvz + cc);
#pragma unroll
        for (int mt = 0; mt < 4; ++mt)
#pragma unroll
            for (int h = 0; h < 2; ++h) {
                acc[mt][nt][h * 2 + 0] += cb.x;
                acc[mt][nt][h * 2 + 1] += cb.y;
            }
    }

    // per-row tile max
#pragma unroll
    for (int mt = 0; mt < 4; ++mt)
#pragma unroll
        for (int h = 0; h < 2; ++h) {
            float mx = -1e30f;
#pragma unroll
            for (int nt = 0; nt < 4; ++nt)
                mx = fmaxf(mx, fmaxf(acc[mt][nt][h * 2], acc[mt][nt][h * 2 + 1]));
            mx = fmaxf(mx, __shfl_xor_sync(0xFFFFFFFFu, mx, 1));
            mx = fmaxf(mx, __shfl_xor_sync(0xFFFFFFFFu, mx, 2));
            if (tg == 0) wred[wcol][wm + mt * 16 + g + h * 8] = mx;
        }
    __syncthreads();
    if (tid < 128)
        mrow[tid] = fmaxf(fmaxf(wred[0][tid], wred[1][tid]),
                          fmaxf(wred[2][tid], wred[3][tid]));
    __syncthreads();

    __half* Pz = P + (size_t)z * NC * NH;
#pragma unroll
    for (int mt = 0; mt < 4; ++mt)
#pragma unroll
        for (int h = 0; h < 2; ++h) {
            const int lr = wm + mt * 16 + g + h * 8;
            const int r = m0 + lr;
            const float m = mrow[lr];
            float rowacc = 0.f;
#pragma unroll
            for (int nt = 0; nt < 4; ++nt) {
                const int cc = n0 + wn + nt * 8 + tg * 2;
                float e0 = __expf(acc[mt][nt][h * 2 + 0] - m);
                float e1 = __expf(acc[mt][nt][h * 2 + 1] - m);
                *(__half2*)(Pz + (size_t)r * NH + cc) =
                    __halves2half2(__float2half_rn(e0), __float2half_rn(e1));
                rowacc += e0 + e1;
            }
            rowacc += __shfl_xor_sync(0xFFFFFFFFu, rowacc, 1);
            rowacc += __shfl_xor_sync(0xFFFFFFFFu, rowacc, 2);
            if (tg == 0) wred[wcol][lr] = rowacc;
        }
    __syncthreads();
    if (tid < 128) {
        const size_t o = ((size_t)z * NTILE + blockIdx.x) * NC + m0 + tid;
        M[o]  = mrow[tid];
        Zp[o] = wred[0][tid] + wred[1][tid] + wred[2][tid] + wred[3][tid];
    }
}

// per-row global max + normalized per-tile factors F = exp(M-m)/Z. grid (NC/256, NL).
__global__ __launch_bounds__(256)
void sfix(const float* __restrict__ M, const float* __restrict__ Zp,
          float* __restrict__ F)
{
    const int z = blockIdx.y;
    const int r = blockIdx.x * 256 + threadIdx.x;
    float m = -1e30f;
    for (int t = 0; t < NTILE; ++t)
        m = fmaxf(m, M[((size_t)z * NTILE + t) * NC + r]);
    float zs = 0.f;
    for (int t = 0; t < NTILE; ++t) {
        const size_t o = ((size_t)z * NTILE + t) * NC + r;
        zs += Zp[o] * __expf(M[o] - m);
    }
    const float inv = 1.f / zs;
    for (int t = 0; t < NTILE; ++t) {
        const size_t o = ((size_t)z * NTILE + t) * NC + r;
        F[o] = __expf(M[o] - m) * inv;
    }
}

// ======================================================================
// Fused AV over all levels with factor folding:
// out[r][n] = bf[n] + sum_z sum_t F[z][t][r] * (P_tile @ VfT_z^T)
// CTA 32x256, K flat over (z, chunks), 2-stage, 256 threads, 2 CTAs/SM.
// Per 128-col tile (2 chunks): accumulate in acc2, flush acc += acc2*F (f32).
// ======================================================================
__global__ __launch_bounds__(256, 2)
void avz_k(const __half* __restrict__ P, const __half* __restrict__ VfT,
           const float* __restrict__ Fz, const float* __restrict__ bf,
           float* __restrict__ out)
{
    extern __shared__ __align__(1024) char smem[];
    __shared__ float Fs[NL * NTILE * AV_BM];   // 24KB
    const int tid  = threadIdx.x;
    const int wid  = tid >> 5;
    const int lane = tid & 31;
    const int n0 = blockIdx.x * AV_BN;
    const int m0 = blockIdx.y * AV_BM;
    const int wn = wid * 32;

    // preload normalized factors for this row band
    for (int i = tid; i < NL * NTILE * AV_BM; i += 256) {
        const int zt = i / AV_BM;
        const int r  = i - zt * AV_BM;
        Fs[i] = Fz[(size_t)zt * NC + m0 + r];
    }

    const u32 sbase = smem_u32(smem);

    float acc[2][4][4], acc2[2][4][4];
#pragma unroll
    for (int i = 0; i < 2; ++i)
#pragma unroll
        for (int j = 0; j < 4; ++j)
#pragma unroll
            for (int h = 0; h < 4; ++h) { acc[i][j][h] = 0.f; acc2[i][j][h] = 0.f; }

    const u32 a_row = lane & 15;
    const u32 a_k   = (lane >> 4) << 3;
    const u32 b_row = ((lane >> 4) << 3) + (lane & 7);
    const u32 b_k   = ((lane >> 3) & 1) << 3;

    const int arow_l = tid >> 3;
    const int ak8    = tid & 7;
    const u32 a_off  = (u32)arow_l * 128 + ((((u32)ak8) ^ ((u32)arow_l & 7)) << 4);

    auto load_chunk = [&](int cg) {
        const int z = cg >> 7;
        const int c = cg & 127;
        const int kb = c * KC;
        const u32 sb = sbase + (cg & 1) * AV_STAGE;
        {   // A: 32 rows x 64 halves, one shot
            const __half* g = P + (size_t)z * NC * NH + (size_t)(m0 + arow_l) * NH
                            + kb + (ak8 << 3);
            asm volatile("cp.async.cg.shared.global [%0], [%1], 16;"
                         :: "r"(sb + a_off), "l"(g));
        }
#pragma unroll
        for (int i = 0; i < 8; ++i) {   // B: 256 rows x 64 halves
            const int cc = i * 256 + tid;
            const int row = cc >> 3;
            const int k8  = cc & 7;
            const __half* g = VfT + (size_t)z * FD * NH + (size_t)(n0 + row) * NH
                            + kb + (k8 << 3);
            const u32 d = sb + AV_TA + row * 128 + (((u32)k8 ^ ((u32)row & 7)) << 4);
            asm volatile("cp.async.cg.shared.global [%0], [%1], 16;" :: "r"(d), "l"(g));
        }
        asm volatile("cp.async.commit_group;" ::: "memory");
    };

    __syncthreads();     // Fs ready
    const int NCHG = NL * (NH / KC);   // 384
    load_chunk(0);

    const int g  = lane >> 2;
    const int tg = lane & 3;

    for (int cg = 0; cg < NCHG; ++cg) {
        if (cg + 1 < NCHG) {
            load_chunk(cg + 1);
            asm volatile("cp.async.wait_group 1;" ::: "memory");
        } else {
            asm volatile("cp.async.wait_group 0;" ::: "memory");
        }
        __syncthreads();

        const u32 sA = sbase + (cg & 1) * AV_STAGE;
        const u32 sB = sA + AV_TA;
#pragma unroll
        for (int ks = 0; ks < 4; ++ks) {
            const u32 kb = ks << 4;
            u32 ah[2][4], bh[2][4];
#pragma unroll
            for (int mt = 0; mt < 2; ++mt)
                ldsm4(ah[mt], swz(sA, mt * 16 + a_row, kb + a_k));
#pragma unroll
            for (int np = 0; np < 2; ++np)
                ldsm4(bh[np], swz(sB, wn + np * 16 + b_row, kb + b_k));
#pragma unroll
            for (int mt = 0; mt < 2; ++mt)
#pragma unroll
                for (int nt = 0; nt < 4; ++nt)
                    mma_f16(acc2[mt][nt], ah[mt], &bh[nt >> 1][(nt & 1) * 2]);
        }
        __syncthreads();

        if (cg & 1) {   // flush 128-col tile: acc += acc2 * F[z][t][row]
            const int z = cg >> 7;
            const int t = (cg & 127) >> 1;
            const int base = (z * NTILE + t) * AV_BM;
#pragma unroll
            for (int mt = 0; mt < 2; ++mt)
#pragma unroll
                for (int h = 0; h < 2; ++h) {
                    const float f = Fs[base + mt * 16 + g + h * 8];
#pragma unroll
                    for (int nt = 0; nt < 4; ++nt) {
                        acc[mt][nt][h * 2 + 0] = fmaf(acc2[mt][nt][h * 2 + 0], f,
                                                      acc[mt][nt][h * 2 + 0]);
                        acc[mt][nt][h * 2 + 1] = fmaf(acc2[mt][nt][h * 2 + 1], f,
                                                      acc[mt][nt][h * 2 + 1]);
                        acc2[mt][nt][h * 2 + 0] = 0.f;
                        acc2[mt][nt][h * 2 + 1] = 0.f;
                    }
                }
        }
    }

#pragma unroll
    for (int mt = 0; mt < 2; ++mt)
#pragma unroll
        for (int nt = 0; nt < 4; ++nt) {
            const int cc = n0 + wn + nt * 8 + tg * 2;
            const float2 b = *(const float2*)(bf + cc);
#pragma unroll
            for (int h = 0; h < 2; ++h) {
                const int r = m0 + mt * 16 + g + h * 8;
                *(float2*)(out + (size_t)r * FD + cc) =
                    make_float2(acc[mt][nt][h * 2 + 0] + b.x,
                                acc[mt][nt][h * 2 + 1] + b.y);
            }
        }
}

// ---------------- small kernels ----------------
__global__ __launch_bounds__(256)
void split_rm(const float* __restrict__ X,
              __nv_bfloat16* __restrict__ hi, __nv_bfloat16* __restrict__ lo)
{
    const size_t i = ((size_t)blockIdx.x * 256 + threadIdx.x) << 2;
    float4 v = *(const float4*)(X + i);
    __nv_bfloat16 h0 = __float2bfloat16(v.x), h1 = __float2bfloat16(v.y);
    __nv_bfloat16 h2 = __float2bfloat16(v.z), h3 = __float2bfloat16(v.w);
    *(__nv_bfloat162*)(hi + i)     = __halves2bfloat162(h0, h1);
    *(__nv_bfloat162*)(hi + i + 2) = __halves2bfloat162(h2, h3);
    *(__nv_bfloat162*)(lo + i)     = __halves2bfloat162(
        __float2bfloat16(v.x - __bfloat162float(h0)), __float2bfloat16(v.y - __bfloat162float(h1)));
    *(__nv_bfloat162*)(lo + i + 2) = __halves2bfloat162(
        __float2bfloat16(v.z - __bfloat162float(h2)), __float2bfloat16(v.w - __bfloat162float(h3)));
}

__global__ __launch_bounds__(256)
void cvt16(const float* __restrict__ X, __half* __restrict__ o)
{
    const size_t i = ((size_t)blockIdx.x * 256 + threadIdx.x) << 2;
    float4 v = *(const float4*)(X + i);
    *(__half2*)(o + i)     = __halves2half2(__float2half_rn(v.x), __float2half_rn(v.y));
    *(__half2*)(o + i + 2) = __halves2half2(__float2half_rn(v.z), __float2half_rn(v.w));
}

__global__ void gmat(const float* __restrict__ W2,
                     __nv_bfloat16* __restrict__ Ghi, __nv_bfloat16* __restrict__ Glo)
{
    const int i = blockIdx.x, l = blockIdx.y, j = threadIdx.x;
    const float* W = W2 + (size_t)l * FD * RD;
    float a = 0.f;
    for (int d = 0; d < FD; ++d) a += W[(size_t)d * RD + i] * W[(size_t)d * RD + j];
    a *= SCALE;
    __nv_bfloat16 h = __float2bfloat16(a);
    const size_t o = (size_t)l * RD * RD + (size_t)i * RD + j;
    Ghi[o] = h;
    Glo[o] = __float2bfloat16(a - __bfloat162float(h));
}

__global__ void vvec(const float* __restrict__ W2, const float* __restrict__ b2,
                     float* __restrict__ v)
{
    const int l = blockIdx.x, r = threadIdx.x;
    const float* W = W2 + (size_t)l * FD * RD;
    const float* b = b2 + (size_t)l * FD;
    float a = 0.f;
    for (int d = 0; d < FD; ++d) a += W[(size_t)d * RD + r] * b[d];
    v[l * RD + r] = a * SCALE;
}

__global__ __launch_bounds__(256)
void cvec_k(const __half* __restrict__ Hhf, const float* __restrict__ v,
            float* __restrict__ cv)
{
    const int z = blockIdx.y;
    const int m = blockIdx.x * 256 + threadIdx.x;
    const __half* h = Hhf + (size_t)z * NH * RD + (size_t)m * RD;
    const float* vz = v + z * RD;
    float a = 0.f;
#pragma unroll
    for (int r = 0; r < RD; r += 2) {
        __half2 p = *(const __half2*)(h + r);
        a += __low2float(p) * vz[r] + __high2float(p) * vz[r + 1];
    }
    cv[(size_t)z * NH + m] = a;
}

// ======================================================================
extern "C" void kernel_launch(void* const* d_in, const int* in_sizes, int n_in,
                              void* d_out, int out_size)
{
    const float* cur  = (const float*)d_in[0];
    const float* hist = (const float*)d_in[1];
    const float* W1   = (const float*)d_in[2];
    const float* b1   = (const float*)d_in[3];
    const float* W2   = (const float*)d_in[4];
    const float* b2   = (const float*)d_in[5];
    const float* Wf   = (const float*)d_in[6];
    const float* bf   = (const float*)d_in[7];
    float* out = (float*)d_out;

    __nv_bfloat16 *Xhi, *Xlo, *W1hi, *W1lo, *Ghi, *Glo, *Hhi, *Hlo;
    __half *Wf16, *X16, *Hhf, *Hcf, *P, *VfT;
    float *v, *cv, *M, *Zp, *F;
    cudaGetSymbolAddress((void**)&Xhi, g_Xhi);   cudaGetSymbolAddress((void**)&Xlo, g_Xlo);
    cudaGetSymbolAddress((void**)&W1hi, g_W1hi); cudaGetSymbolAddress((void**)&W1lo, g_W1lo);
    cudaGetSymbolAddress((void**)&Ghi, g_Ghi);   cudaGetSymbolAddress((void**)&Glo, g_Glo);
    cudaGetSymbolAddress((void**)&Hhi, g_Hhi);   cudaGetSymbolAddress((void**)&Hlo, g_Hlo);
    cudaGetSymbolAddress((void**)&Wf16, g_Wf16); cudaGetSymbolAddress((void**)&X16, g_X16);
    cudaGetSymbolAddress((void**)&Hhf, g_Hhf);   cudaGetSymbolAddress((void**)&Hcf, g_Hcf);
    cudaGetSymbolAddress((void**)&P, g_P);       cudaGetSymbolAddress((void**)&VfT, g_VfT);
    cudaGetSymbolAddress((void**)&v, g_v);       cudaGetSymbolAddress((void**)&cv, g_cv);
    cudaGetSymbolAddress((void**)&M, g_M);       cudaGetSymbolAddress((void**)&Zp, g_Zp);
    cudaGetSymbolAddress((void**)&F, g_F);

    cudaFuncSetAttribute(mm128b<true,  1>, cudaFuncAttributeMaxDynamicSharedMemorySize, GSMEM_B);
    cudaFuncSetAttribute(mm128b<false, 2>, cudaFuncAttributeMaxDynamicSharedMemorySize, GSMEM_B);
    cudaFuncSetAttribute(vft_k,  cudaFuncAttributeMaxDynamicSharedMemorySize, GSMEM_V);
    cudaFuncSetAttribute(sexp_k, cudaFuncAttributeMaxDynamicSharedMemorySize, GSMEM_SX);
    cudaFuncSetAttribute(avz_k,  cudaFuncAttributeMaxDynamicSharedMemorySize, GSMEM_AV);

    // ---- preprocessing ----
    split_rm<<<(NC * FD) / 1024, 256>>>(cur,  Xhi,                   Xlo);
    split_rm<<<(NH * FD) / 1024, 256>>>(hist, Xhi + (size_t)NC * FD, Xlo + (size_t)NC * FD);
    split_rm<<<(NL * RD * FD) / 1024, 256>>>(W1, W1hi, W1lo);
    cvt16<<<(FD * NL * FD) / 1024, 256>>>(Wf, Wf16);
    cvt16<<<(NH * FD) / 1024, 256>>>(hist, X16);
    gmat<<<dim3(RD, NL), RD>>>(W2, Ghi, Glo);
    vvec<<<NL, RD>>>(W2, b2, v);

    // VfT_l = Wf_l @ hist^T  [FD, NH] fp16-1
    vft_k<<<dim3(NH / 128, FD / 128, NL), 256, GSMEM_V>>>(Wf16, X16, VfT);

    // H_l = relu(X @ W1_l^T + b1_l): split (rows<NC) + fp16 (rows>=NC)
    mm128b<true, 1><<<dim3(RD / 128, NT / 128, NL), 256, GSMEM_B>>>(
        Xhi, Xlo, 0, FD,
        W1hi, W1lo, (size_t)RD * FD, FD,
        b1, (size_t)RD,
        Hhi, Hlo, (size_t)NT * RD, RD,
        Hhf, (size_t)NH * RD, RD, FD);

    // cv[z] = Hhf[z] . v[z]
    cvec_k<<<dim3(NH / 256, NL), 256>>>(Hhf, v, cv);

    // Hc'_l = Hc_l @ G_l (pre-scaled)  [NC, RD] fp16
    mm128b<false, 2><<<dim3(RD / 128, NC / 128, NL), 256, GSMEM_B>>>(
        Hhi, Hlo, (size_t)NT * RD, RD,
        Ghi, Glo, (size_t)RD * RD, RD,
        nullptr, 0,
        nullptr, nullptr, 0, 0,
        Hcf, (size_t)NC * RD, RD, RD);

    // P = exp(s - m_tile); M, Zp partials
    sexp_k<<<dim3(NH / 128, NC / 128, NL), 256, GSMEM_SX>>>(Hcf, Hhf, cv, P, M, Zp);

    // normalized per-tile factors F = exp(M - m) / Z
    sfix<<<dim3(NC / 256, NL), 256>>>(M, Zp, F);

    // out = bf + sum_z sum_t F * (P_tile @ VfT^T)
    avz_k<<<dim3(FD / AV_BN, NC / AV_BM), 256, GSMEM_AV>>>(P, VfT, F, bf, out);
}